// round 2
// baseline (speedup 1.0000x reference)
#include <cuda_runtime.h>
#include <math.h>

#define HOx 64
#define WOx 64
#define DIMX 128
#define BATCH 4
#define NP (HOx*WOx)            /* 4096  */
#define NTOK (BATCH*NP)         /* 16384 */
#define NTOKIN (BATCH*128*128)  /* 65536 */

// ---------------- scratch (static device globals; no runtime alloc) ----------------
__device__ float g_xn[(size_t)NTOKIN*DIMX];
__device__ float g_k [(size_t)NTOKIN*DIMX];
__device__ float g_v [(size_t)NTOKIN*DIMX];
__device__ float g_q  [(size_t)NTOK*DIMX];
__device__ float g_qln[(size_t)NTOK*DIMX];
__device__ float g_seed[(size_t)NTOK*DIMX];
__device__ float g_h [(size_t)NTOK*2*DIMX];
__device__ float g_h2[(size_t)NTOK*DIMX];
__device__ float g_cs[NTOK];
__device__ float g_wc[9*DIMX*DIMX];
__device__ int   g_rows[9*NTOK];

// ---------------- prep: transpose conv weights + conv row-gather table ----------------
__global__ void prep_conv(const float* __restrict__ conv_w)
{
    int i = blockIdx.x * blockDim.x + threadIdx.x;
    if (i < 9*DIMX*DIMX) {
        int kk = i / (DIMX*DIMX);
        int r  = i % (DIMX*DIMX);
        int c  = r / DIMX, dout = r % DIMX;
        int ky = kk / 3, kx = kk % 3;
        g_wc[i] = conv_w[((dout*DIMX + c)*3 + ky)*3 + kx];
    }
    if (i < 9*NTOK) {
        int kk = i / NTOK;
        int m  = i % NTOK;
        int b  = m >> 12, p = m & 4095;
        int ho = p >> 6, wo = p & 63;
        int ky = kk / 3, kx = kk % 3;
        int y = 2*ho - 1 + ky;
        int x = 2*wo - 1 + kx;
        g_rows[i] = (y >= 0 && y < 128 && x >= 0 && x < 128) ? (b*16384 + y*128 + x) : -1;
    }
}

// ---------------- LayerNorm over DIM=128 (one warp per row) ----------------
__global__ void ln_kernel(const float* __restrict__ in, float* __restrict__ out,
                          const float* __restrict__ gamma, const float* __restrict__ beta,
                          int nrows, int add_residual)
{
    int row  = (blockIdx.x * blockDim.x + threadIdx.x) >> 5;
    int lane = threadIdx.x & 31;
    if (row >= nrows) return;
    const float4* ip = (const float4*)(in + (size_t)row * DIMX);
    float4 v = ip[lane];
    float s  = v.x + v.y + v.z + v.w;
    float sq = v.x*v.x + v.y*v.y + v.z*v.z + v.w*v.w;
    #pragma unroll
    for (int o = 16; o > 0; o >>= 1) {
        s  += __shfl_xor_sync(0xffffffffu, s,  o);
        sq += __shfl_xor_sync(0xffffffffu, sq, o);
    }
    float mu  = s * (1.0f/DIMX);
    float var = sq * (1.0f/DIMX) - mu*mu;
    float rs  = rsqrtf(var + 1e-5f);
    float4 g4 = ((const float4*)gamma)[lane];
    float4 b4 = ((const float4*)beta)[lane];
    float4 o4;
    o4.x = (v.x - mu)*rs*g4.x + b4.x;
    o4.y = (v.y - mu)*rs*g4.y + b4.y;
    o4.z = (v.z - mu)*rs*g4.z + b4.z;
    o4.w = (v.w - mu)*rs*g4.w + b4.w;
    float4* op = (float4*)(out + (size_t)row * DIMX);
    if (add_residual) {
        float4 e = op[lane];
        o4.x += e.x; o4.y += e.y; o4.z += e.z; o4.w += e.w;
    }
    op[lane] = o4;
}

// ---------------- tiled SGEMM: C[M,N] = gather(A)[M,K] @ B[K,N] (+bias)(+gelu)(+=C) ----------------
__device__ __forceinline__ float gelu_exact(float x)
{
    return 0.5f * x * (1.0f + erff(x * 0.70710678118654752f));
}

__global__ __launch_bounds__(256)
void sgemm(int M, int N, int K,
           const float* __restrict__ A, const float* __restrict__ B, float* __restrict__ C,
           const int* __restrict__ rowidx, const float* __restrict__ bias,
           int act, int accum)
{
    __shared__ __align__(16) float As[8][128];
    __shared__ __align__(16) float Bs[8][128];
    int tid  = threadIdx.x;
    int brow = blockIdx.y * 128;
    int bcol = blockIdx.x * 128;

    int arow = tid >> 1;
    int ak   = (tid & 1) << 2;
    int grow = brow + arow;
    int srow = rowidx ? rowidx[grow] : grow;
    const float* Ap = (srow >= 0) ? (A + (size_t)srow * K + ak) : 0;

    int brr = tid >> 5;
    int bcc = (tid & 31) << 2;
    const float* Bp = B + (size_t)brr * N + bcol + bcc;

    float acc[8][8];
    #pragma unroll
    for (int i = 0; i < 8; i++)
        #pragma unroll
        for (int j = 0; j < 8; j++) acc[i][j] = 0.0f;

    int tr = (tid >> 4) << 3;
    int tc = (tid & 15) << 3;

    for (int k0 = 0; k0 < K; k0 += 8) {
        float4 av = Ap ? *(const float4*)(Ap + k0) : make_float4(0.f,0.f,0.f,0.f);
        As[ak+0][arow] = av.x; As[ak+1][arow] = av.y;
        As[ak+2][arow] = av.z; As[ak+3][arow] = av.w;
        *(float4*)&Bs[brr][bcc] = *(const float4*)(Bp + (size_t)k0 * N);
        __syncthreads();
        #pragma unroll
        for (int kk = 0; kk < 8; kk++) {
            float4 a0 = *(const float4*)&As[kk][tr];
            float4 a1 = *(const float4*)&As[kk][tr+4];
            float4 b0 = *(const float4*)&Bs[kk][tc];
            float4 b1 = *(const float4*)&Bs[kk][tc+4];
            float ar[8] = {a0.x,a0.y,a0.z,a0.w,a1.x,a1.y,a1.z,a1.w};
            float br[8] = {b0.x,b0.y,b0.z,b0.w,b1.x,b1.y,b1.z,b1.w};
            #pragma unroll
            for (int i = 0; i < 8; i++)
                #pragma unroll
                for (int j = 0; j < 8; j++)
                    acc[i][j] = fmaf(ar[i], br[j], acc[i][j]);
        }
        __syncthreads();
    }

    #pragma unroll
    for (int i = 0; i < 8; i++) {
        int row = brow + tr + i;
        #pragma unroll
        for (int j = 0; j < 8; j++) {
            int col = bcol + tc + j;
            float c = acc[i][j];
            if (bias) c += bias[col];
            if (act)  c = gelu_exact(c);
            size_t off = (size_t)row * N + col;
            if (accum) c += C[off];
            C[off] = c;
        }
    }
}

// ---------------- attention: dots + softmax + eps, atomic col sums ----------------
__global__ __launch_bounds__(128)
void attn_kernel(const float* __restrict__ Kv, const float* __restrict__ Qv,
                 const float* __restrict__ rpb, const float* __restrict__ tau,
                 float* __restrict__ attn_out, float* __restrict__ colsums)
{
    int bp = blockIdx.x;
    int b = bp >> 12, p = bp & 4095;
    int h = p >> 6, w = p & 63;
    int hc = min(max(h,1),62), wc = min(max(w,1),62);

    __shared__ __align__(16) float q_sh[9][128];
    int tid = threadIdx.x;
    #pragma unroll
    for (int t = 0; t < 9; t++) {
        int np = (hc + t/3 - 1)*64 + (wc + t%3 - 1);
        q_sh[t][tid] = Qv[((size_t)(b<<12) + np)*DIMX + tid];
    }
    __syncthreads();

    int g = tid >> 5, lane = tid & 31;
    int tin = (2*h + (g>>1))*128 + 2*w + (g&1);
    float4 kv = *(const float4*)(Kv + ((size_t)(b*16384 + tin))*DIMX + lane*4);

    float myd = 0.0f;
    #pragma unroll
    for (int t = 0; t < 9; t++) {
        float4 qv = *(const float4*)(&q_sh[t][lane*4]);
        float d = kv.x*qv.x + kv.y*qv.y + kv.z*qv.z + kv.w*qv.w;
        #pragma unroll
        for (int o = 16; o > 0; o >>= 1) d += __shfl_xor_sync(0xffffffffu, d, o);
        if (lane == t) myd = d;
    }

    float scale = expf(*tau);
    float z = (lane < 9) ? (myd + rpb[g*9 + lane]) * scale : -1e30f;
    float m = z;
    #pragma unroll
    for (int o = 16; o > 0; o >>= 1) m = fmaxf(m, __shfl_xor_sync(0xffffffffu, m, o));
    float e = (lane < 9) ? expf(z - m) : 0.0f;
    float s = e;
    #pragma unroll
    for (int o = 16; o > 0; o >>= 1) s += __shfl_xor_sync(0xffffffffu, s, o);

    if (lane < 9) {
        float a = e / s + 1e-6f;
        attn_out[(((size_t)(b*4 + g))*4096 + p)*9 + lane] = a;
        int np = (hc + lane/3 - 1)*64 + (wc + lane%3 - 1);
        atomicAdd(&colsums[(b<<12) + np], a);
    }
}

// ---------------- column-normalize + weighted v gather; x_out += upd ----------------
__global__ __launch_bounds__(128)
void upd_kernel(const float* __restrict__ attn_out, const float* __restrict__ colsums,
                const float* __restrict__ Vv, float* __restrict__ acol_out,
                float* __restrict__ x_out)
{
    int bp = blockIdx.x;
    int b = bp >> 12, p = bp & 4095;
    int h = p >> 6, w = p & 63;
    int hc = min(max(h,1),62), wc = min(max(w,1),62);

    __shared__ float sA[36];
    int tid = threadIdx.x;
    if (tid < 36) {
        int g = tid / 9, t = tid % 9;
        float a  = attn_out[(((size_t)(b*4 + g))*4096 + p)*9 + t];
        int np   = (hc + t/3 - 1)*64 + (wc + t%3 - 1);
        float cs = colsums[(b<<12) + np];
        float val = a / (cs + 1e-8f);
        sA[tid] = val;
        acol_out[(((size_t)(b*4 + g))*4096 + p)*9 + t] = val;
    }
    __syncthreads();

    float acc = 0.0f;
    #pragma unroll
    for (int g = 0; g < 4; g++) {
        #pragma unroll
        for (int t = 0; t < 9; t++) {
            int nh = hc + t/3 - 1, nw = wc + t%3 - 1;
            int tin = (2*nh + (g>>1))*128 + 2*nw + (g&1);
            acc += sA[g*9 + t] * Vv[((size_t)(b*16384 + tin))*DIMX + tid];
        }
    }
    x_out[((size_t)(b<<12) + p)*DIMX + tid] += acc;
}

// ---------------- launcher ----------------
extern "C" void kernel_launch(void* const* d_in, const int* in_sizes, int n_in,
                              void* d_out, int out_size)
{
    (void)in_sizes; (void)n_in; (void)out_size;
    const float* x        = (const float*)d_in[0];
    const float* conv_w   = (const float*)d_in[1];
    const float* q_w      = (const float*)d_in[2];
    const float* k_w      = (const float*)d_in[3];
    const float* v_w      = (const float*)d_in[4];
    const float* mlp_w1   = (const float*)d_in[5];
    const float* mlp_b1   = (const float*)d_in[6];
    const float* mlp_w2   = (const float*)d_in[7];
    const float* mlp_b2   = (const float*)d_in[8];
    const float* ln_in_g  = (const float*)d_in[9];
    const float* ln_in_b  = (const float*)d_in[10];
    const float* ln_out_g = (const float*)d_in[11];
    const float* ln_out_b = (const float*)d_in[12];
    const float* tau      = (const float*)d_in[13];
    const float* rpb      = (const float*)d_in[14];

    float* xout     = (float*)d_out;                       // (B, 4096, 128)
    float* attn_out = xout + (size_t)NTOK * DIMX;          // (B, 4, 64, 64, 9)
    float* acol_out = attn_out + (size_t)BATCH * 4 * NP * 9;

    float *p_xn, *p_k, *p_v, *p_q, *p_qln, *p_seed, *p_h, *p_h2, *p_cs, *p_wc;
    int* p_rows;
    cudaGetSymbolAddress((void**)&p_xn,  g_xn);
    cudaGetSymbolAddress((void**)&p_k,   g_k);
    cudaGetSymbolAddress((void**)&p_v,   g_v);
    cudaGetSymbolAddress((void**)&p_q,   g_q);
    cudaGetSymbolAddress((void**)&p_qln, g_qln);
    cudaGetSymbolAddress((void**)&p_seed,g_seed);
    cudaGetSymbolAddress((void**)&p_h,   g_h);
    cudaGetSymbolAddress((void**)&p_h2,  g_h2);
    cudaGetSymbolAddress((void**)&p_cs,  g_cs);
    cudaGetSymbolAddress((void**)&p_wc,  g_wc);
    cudaGetSymbolAddress((void**)&p_rows,g_rows);

    // prep
    prep_conv<<<(9*NTOK + 255)/256, 256>>>(conv_w);
    // xn = LN(x, ln_in)
    ln_kernel<<<NTOKIN/8, 256>>>(x, p_xn, ln_in_g, ln_in_b, NTOKIN, 0);
    // k = xn @ k_w ; v = x @ v_w
    dim3 gbig(1, NTOKIN/128);
    sgemm<<<gbig, 256>>>(NTOKIN, 128, 128, p_xn, k_w, p_k, 0, 0, 0, 0);
    sgemm<<<gbig, 256>>>(NTOKIN, 128, 128, x,    v_w, p_v, 0, 0, 0, 0);
    // conv via 9 row-gathered GEMMs accumulating into seed
    dim3 gsm(1, NTOK/128);
    for (int kk = 0; kk < 9; kk++)
        sgemm<<<gsm, 256>>>(NTOK, 128, 128, x, p_wc + kk*DIMX*DIMX, p_seed,
                            p_rows + kk*NTOK, 0, 0, kk ? 1 : 0);
    // x_out = LN(seed, ln_out)
    ln_kernel<<<NTOK/8, 256>>>(p_seed, xout, ln_out_g, ln_out_b, NTOK, 0);

    for (int it = 0; it < 3; it++) {
        ln_kernel<<<NTOK/8, 256>>>(xout, p_qln, ln_out_g, ln_out_b, NTOK, 0);
        sgemm<<<gsm, 256>>>(NTOK, 128, 128, p_qln, q_w, p_q, 0, 0, 0, 0);
        cudaMemsetAsync(p_cs, 0, NTOK * sizeof(float));
        attn_kernel<<<NTOK, 128>>>(p_k, p_q, rpb, tau, attn_out, p_cs);
        upd_kernel<<<NTOK, 128>>>(attn_out, p_cs, p_v, acol_out, xout);
        sgemm<<<dim3(2, NTOK/128), 256>>>(NTOK, 256, 128, xout, mlp_w1, p_h, 0, mlp_b1, 1, 0);
        sgemm<<<gsm, 256>>>(NTOK, 128, 256, p_h, mlp_w2, p_h2, 0, mlp_b2, 0, 0);
        ln_kernel<<<NTOK/8, 256>>>(p_h2, xout, ln_out_g, ln_out_b, NTOK, 1);
    }
}

// round 3
// speedup vs baseline: 1.1815x; 1.1815x over previous
#include <cuda_runtime.h>
#include <math.h>

#define HOx 64
#define WOx 64
#define DIMX 128
#define BATCH 4
#define NP (HOx*WOx)            /* 4096  */
#define NTOK (BATCH*NP)         /* 16384 */
#define NTOKIN (BATCH*128*128)  /* 65536 */

// ---------------- scratch (static device globals; no runtime alloc) ----------------
__device__ float g_xn[(size_t)NTOKIN*DIMX];
__device__ float g_k [(size_t)NTOKIN*DIMX];
__device__ float g_v [(size_t)NTOKIN*DIMX];
__device__ float g_q  [(size_t)NTOK*DIMX];
__device__ float g_qln[(size_t)NTOK*DIMX];
__device__ float g_seed[(size_t)NTOK*DIMX];
__device__ float g_h [(size_t)NTOK*2*DIMX];
__device__ float g_h2[(size_t)NTOK*DIMX];
__device__ float g_cs[NTOK];
__device__ float g_wc[9*DIMX*DIMX];
__device__ int   g_rows[9*NTOK];

// ---------------- packed f32x2 helpers ----------------
__device__ __forceinline__ void ffma2(unsigned long long& c, unsigned long long a, unsigned long long b)
{
    asm("fma.rn.f32x2 %0, %1, %2, %0;" : "+l"(c) : "l"(a), "l"(b));
}
__device__ __forceinline__ unsigned long long splat2(float x)
{
    unsigned long long r;
    asm("mov.b64 %0, {%1, %1};" : "=l"(r) : "f"(x));
    return r;
}
__device__ __forceinline__ float2 unpack2(unsigned long long v)
{
    float2 f;
    asm("mov.b64 {%0, %1}, %2;" : "=f"(f.x), "=f"(f.y) : "l"(v));
    return f;
}

// ---------------- prep: transpose conv weights + conv row-gather table ----------------
__global__ void prep_conv(const float* __restrict__ conv_w)
{
    int i = blockIdx.x * blockDim.x + threadIdx.x;
    if (i < 9*DIMX*DIMX) {
        int kk = i / (DIMX*DIMX);
        int r  = i % (DIMX*DIMX);
        int c  = r / DIMX, dout = r % DIMX;
        int ky = kk / 3, kx = kk % 3;
        g_wc[i] = conv_w[((dout*DIMX + c)*3 + ky)*3 + kx];
    }
    if (i < 9*NTOK) {
        int kk = i / NTOK;
        int m  = i % NTOK;
        int b  = m >> 12, p = m & 4095;
        int ho = p >> 6, wo = p & 63;
        int ky = kk / 3, kx = kk % 3;
        int y = 2*ho - 1 + ky;
        int x = 2*wo - 1 + kx;
        g_rows[i] = (y >= 0 && y < 128 && x >= 0 && x < 128) ? (b*16384 + y*128 + x) : -1;
    }
}

// ---------------- LayerNorm over DIM=128 (one warp per row) ----------------
__global__ void ln_kernel(const float* __restrict__ in, float* __restrict__ out,
                          const float* __restrict__ gamma, const float* __restrict__ beta,
                          int nrows, int add_residual)
{
    int row  = (blockIdx.x * blockDim.x + threadIdx.x) >> 5;
    int lane = threadIdx.x & 31;
    if (row >= nrows) return;
    const float4* ip = (const float4*)(in + (size_t)row * DIMX);
    float4 v = ip[lane];
    float s  = v.x + v.y + v.z + v.w;
    float sq = v.x*v.x + v.y*v.y + v.z*v.z + v.w*v.w;
    #pragma unroll
    for (int o = 16; o > 0; o >>= 1) {
        s  += __shfl_xor_sync(0xffffffffu, s,  o);
        sq += __shfl_xor_sync(0xffffffffu, sq, o);
    }
    float mu  = s * (1.0f/DIMX);
    float var = sq * (1.0f/DIMX) - mu*mu;
    float rs  = rsqrtf(var + 1e-5f);
    float4 g4 = ((const float4*)gamma)[lane];
    float4 b4 = ((const float4*)beta)[lane];
    float4 o4;
    o4.x = (v.x - mu)*rs*g4.x + b4.x;
    o4.y = (v.y - mu)*rs*g4.y + b4.y;
    o4.z = (v.z - mu)*rs*g4.z + b4.z;
    o4.w = (v.w - mu)*rs*g4.w + b4.w;
    float4* op = (float4*)(out + (size_t)row * DIMX);
    if (add_residual) {
        float4 e = op[lane];
        o4.x += e.x; o4.y += e.y; o4.z += e.z; o4.w += e.w;
    }
    op[lane] = o4;
}

__device__ __forceinline__ float gelu_exact(float x)
{
    return 0.5f * x * (1.0f + erff(x * 0.70710678118654752f));
}

// ---------------- tiled SGEMM, BMx128 tiles, f32x2 inner, double-buffered ----------------
// C[M,N] = sum_seg gather(A, rowidx[seg])[M,K] @ B[seg][K,N]   (+bias)(+gelu)
// kshift: log2(K/8). rowidx may be null (identity rows, single gather table per seg).
template<int BM>
__global__ __launch_bounds__(BM*2)
void sgemm_t(int M, int N, int K, int ksegs, int kshift,
             const float* __restrict__ A, const float* __restrict__ B,
             float* __restrict__ C,
             const int* __restrict__ rowidx, const float* __restrict__ bias,
             int act)
{
    __shared__ __align__(16) float As[2][8][BM];
    __shared__ __align__(16) float Bs[2][8][128];

    const int tid  = threadIdx.x;
    const int brow = blockIdx.y * BM;
    const int bcol = blockIdx.x * 128;

    // A-load mapping: 2 threads per row, each loads float4 of 4 k-values
    const int arow = tid >> 1;
    const int ak   = (tid & 1) << 2;

    // B-load mapping
    int brr, bcc;
    if (BM == 128) { brr = tid >> 5; bcc = (tid & 31) << 2; }
    else           { brr = tid >> 4; bcc = (tid & 15) << 3; }

    const int kmask = (1 << kshift) - 1;
    const int T = ksegs << kshift;

    // staging regs
    float4 avR, bv0R, bv1R;

    auto gload = [&](int t) {
        int seg = t >> kshift;
        int k0  = (t & kmask) << 3;
        int srow;
        if (rowidx) srow = rowidx[seg * M + brow + arow];
        else        srow = brow + arow;
        if (srow >= 0)
            avR = *(const float4*)(A + (size_t)srow * K + k0 + ak);
        else
            avR = make_float4(0.f, 0.f, 0.f, 0.f);
        const float* Bp = B + (size_t)seg * K * N + (size_t)(k0 + brr) * N + bcol + bcc;
        bv0R = *(const float4*)Bp;
        if (BM == 64) bv1R = *(const float4*)(Bp + 4);
    };
    auto sts = [&](int nb) {
        As[nb][ak+0][arow] = avR.x; As[nb][ak+1][arow] = avR.y;
        As[nb][ak+2][arow] = avR.z; As[nb][ak+3][arow] = avR.w;
        *(float4*)&Bs[nb][brr][bcc] = bv0R;
        if (BM == 64) *(float4*)&Bs[nb][brr][bcc+4] = bv1R;
    };

    unsigned long long acc[8][4];
    #pragma unroll
    for (int i = 0; i < 8; i++)
        #pragma unroll
        for (int j = 0; j < 4; j++) acc[i][j] = 0ull;

    const int tr = (tid >> 4) << 3;
    const int tc = (tid & 15) << 3;

    gload(0);
    sts(0);
    __syncthreads();
    int buf = 0;

    for (int t = 0; t < T; t++) {
        if (t + 1 < T) gload(t + 1);
        #pragma unroll
        for (int kk = 0; kk < 8; kk++) {
            float4 a0 = *(const float4*)&As[buf][kk][tr];
            float4 a1 = *(const float4*)&As[buf][kk][tr+4];
            ulonglong2 bb01 = *(const ulonglong2*)&Bs[buf][kk][tc];
            ulonglong2 bb23 = *(const ulonglong2*)&Bs[buf][kk][tc+4];
            float ar[8] = {a0.x,a0.y,a0.z,a0.w,a1.x,a1.y,a1.z,a1.w};
            #pragma unroll
            for (int i = 0; i < 8; i++) {
                unsigned long long aa = splat2(ar[i]);
                ffma2(acc[i][0], aa, bb01.x);
                ffma2(acc[i][1], aa, bb01.y);
                ffma2(acc[i][2], aa, bb23.x);
                ffma2(acc[i][3], aa, bb23.y);
            }
        }
        if (t + 1 < T) {
            sts(buf ^ 1);
            __syncthreads();
            buf ^= 1;
        }
    }

    // epilogue
    #pragma unroll
    for (int i = 0; i < 8; i++) {
        int row = brow + tr + i;
        float out[8];
        #pragma unroll
        for (int j = 0; j < 4; j++) {
            float2 v = unpack2(acc[i][j]);
            out[2*j]   = v.x;
            out[2*j+1] = v.y;
        }
        if (bias) {
            #pragma unroll
            for (int j = 0; j < 8; j++) out[j] += bias[bcol + tc + j];
        }
        if (act) {
            #pragma unroll
            for (int j = 0; j < 8; j++) out[j] = gelu_exact(out[j]);
        }
        float* Cp = C + (size_t)row * N + bcol + tc;
        *(float4*)Cp       = make_float4(out[0], out[1], out[2], out[3]);
        *(float4*)(Cp + 4) = make_float4(out[4], out[5], out[6], out[7]);
    }
}

// ---------------- attention: dots + softmax + eps, atomic col sums ----------------
__global__ __launch_bounds__(128)
void attn_kernel(const float* __restrict__ Kv, const float* __restrict__ Qv,
                 const float* __restrict__ rpb, const float* __restrict__ tau,
                 float* __restrict__ attn_out, float* __restrict__ colsums)
{
    int bp = blockIdx.x;
    int b = bp >> 12, p = bp & 4095;
    int h = p >> 6, w = p & 63;
    int hc = min(max(h,1),62), wc = min(max(w,1),62);

    __shared__ __align__(16) float q_sh[9][128];
    int tid = threadIdx.x;
    #pragma unroll
    for (int t = 0; t < 9; t++) {
        int np = (hc + t/3 - 1)*64 + (wc + t%3 - 1);
        q_sh[t][tid] = Qv[((size_t)(b<<12) + np)*DIMX + tid];
    }
    __syncthreads();

    int g = tid >> 5, lane = tid & 31;
    int tin = (2*h + (g>>1))*128 + 2*w + (g&1);
    float4 kv = *(const float4*)(Kv + ((size_t)(b*16384 + tin))*DIMX + lane*4);

    float myd = 0.0f;
    #pragma unroll
    for (int t = 0; t < 9; t++) {
        float4 qv = *(const float4*)(&q_sh[t][lane*4]);
        float d = kv.x*qv.x + kv.y*qv.y + kv.z*qv.z + kv.w*qv.w;
        #pragma unroll
        for (int o = 16; o > 0; o >>= 1) d += __shfl_xor_sync(0xffffffffu, d, o);
        if (lane == t) myd = d;
    }

    float scale = expf(*tau);
    float z = (lane < 9) ? (myd + rpb[g*9 + lane]) * scale : -1e30f;
    float m = z;
    #pragma unroll
    for (int o = 16; o > 0; o >>= 1) m = fmaxf(m, __shfl_xor_sync(0xffffffffu, m, o));
    float e = (lane < 9) ? expf(z - m) : 0.0f;
    float s = e;
    #pragma unroll
    for (int o = 16; o > 0; o >>= 1) s += __shfl_xor_sync(0xffffffffu, s, o);

    if (lane < 9) {
        float a = e / s + 1e-6f;
        attn_out[(((size_t)(b*4 + g))*4096 + p)*9 + lane] = a;
        int np = (hc + lane/3 - 1)*64 + (wc + lane%3 - 1);
        atomicAdd(&colsums[(b<<12) + np], a);
    }
}

// ---------------- column-normalize + weighted v gather; x_out += upd ----------------
__global__ __launch_bounds__(128)
void upd_kernel(const float* __restrict__ attn_out, const float* __restrict__ colsums,
                const float* __restrict__ Vv, float* __restrict__ acol_out,
                float* __restrict__ x_out)
{
    int bp = blockIdx.x;
    int b = bp >> 12, p = bp & 4095;
    int h = p >> 6, w = p & 63;
    int hc = min(max(h,1),62), wc = min(max(w,1),62);

    __shared__ float sA[36];
    int tid = threadIdx.x;
    if (tid < 36) {
        int g = tid / 9, t = tid % 9;
        float a  = attn_out[(((size_t)(b*4 + g))*4096 + p)*9 + t];
        int np   = (hc + t/3 - 1)*64 + (wc + t%3 - 1);
        float cs = colsums[(b<<12) + np];
        float val = a / (cs + 1e-8f);
        sA[tid] = val;
        acol_out[(((size_t)(b*4 + g))*4096 + p)*9 + t] = val;
    }
    __syncthreads();

    float acc = 0.0f;
    #pragma unroll
    for (int g = 0; g < 4; g++) {
        #pragma unroll
        for (int t = 0; t < 9; t++) {
            int nh = hc + t/3 - 1, nw = wc + t%3 - 1;
            int tin = (2*nh + (g>>1))*128 + 2*nw + (g&1);
            acc += sA[g*9 + t] * Vv[((size_t)(b*16384 + tin))*DIMX + tid];
        }
    }
    x_out[((size_t)(b<<12) + p)*DIMX + tid] += acc;
}

// ---------------- launcher ----------------
extern "C" void kernel_launch(void* const* d_in, const int* in_sizes, int n_in,
                              void* d_out, int out_size)
{
    (void)in_sizes; (void)n_in; (void)out_size;
    const float* x        = (const float*)d_in[0];
    const float* conv_w   = (const float*)d_in[1];
    const float* q_w      = (const float*)d_in[2];
    const float* k_w      = (const float*)d_in[3];
    const float* v_w      = (const float*)d_in[4];
    const float* mlp_w1   = (const float*)d_in[5];
    const float* mlp_b1   = (const float*)d_in[6];
    const float* mlp_w2   = (const float*)d_in[7];
    const float* mlp_b2   = (const float*)d_in[8];
    const float* ln_in_g  = (const float*)d_in[9];
    const float* ln_in_b  = (const float*)d_in[10];
    const float* ln_out_g = (const float*)d_in[11];
    const float* ln_out_b = (const float*)d_in[12];
    const float* tau      = (const float*)d_in[13];
    const float* rpb      = (const float*)d_in[14];

    float* xout     = (float*)d_out;                       // (B, 4096, 128)
    float* attn_out = xout + (size_t)NTOK * DIMX;          // (B, 4, 64, 64, 9)
    float* acol_out = attn_out + (size_t)BATCH * 4 * NP * 9;

    float *p_xn, *p_k, *p_v, *p_q, *p_qln, *p_seed, *p_h, *p_h2, *p_cs, *p_wc;
    int* p_rows;
    cudaGetSymbolAddress((void**)&p_xn,  g_xn);
    cudaGetSymbolAddress((void**)&p_k,   g_k);
    cudaGetSymbolAddress((void**)&p_v,   g_v);
    cudaGetSymbolAddress((void**)&p_q,   g_q);
    cudaGetSymbolAddress((void**)&p_qln, g_qln);
    cudaGetSymbolAddress((void**)&p_seed,g_seed);
    cudaGetSymbolAddress((void**)&p_h,   g_h);
    cudaGetSymbolAddress((void**)&p_h2,  g_h2);
    cudaGetSymbolAddress((void**)&p_cs,  g_cs);
    cudaGetSymbolAddress((void**)&p_wc,  g_wc);
    cudaGetSymbolAddress((void**)&p_rows,g_rows);

    // prep
    prep_conv<<<(9*NTOK + 255)/256, 256>>>(conv_w);
    // xn = LN(x, ln_in)
    ln_kernel<<<NTOKIN/8, 256>>>(x, p_xn, ln_in_g, ln_in_b, NTOKIN, 0);
    // k = xn @ k_w ; v = x @ v_w   (BM=128, 512 blocks)
    dim3 gbig(1, NTOKIN/128);
    sgemm_t<128><<<gbig, 256>>>(NTOKIN, 128, 128, 1, 4, p_xn, k_w, p_k, 0, 0, 0);
    sgemm_t<128><<<gbig, 256>>>(NTOKIN, 128, 128, 1, 4, x,    v_w, p_v, 0, 0, 0);
    // conv: single fused kernel, 9 K-segments with row gather (BM=64, 256 blocks)
    dim3 gsm(1, NTOK/64);
    sgemm_t<64><<<gsm, 128>>>(NTOK, 128, 128, 9, 4, x, p_wc, p_seed, p_rows, 0, 0);
    // x_out = LN(seed, ln_out)
    ln_kernel<<<NTOK/8, 256>>>(p_seed, xout, ln_out_g, ln_out_b, NTOK, 0);

    for (int it = 0; it < 3; it++) {
        ln_kernel<<<NTOK/8, 256>>>(xout, p_qln, ln_out_g, ln_out_b, NTOK, 0);
        sgemm_t<64><<<gsm, 128>>>(NTOK, 128, 128, 1, 4, p_qln, q_w, p_q, 0, 0, 0);
        cudaMemsetAsync(p_cs, 0, NTOK * sizeof(float));
        attn_kernel<<<NTOK, 128>>>(p_k, p_q, rpb, tau, attn_out, p_cs);
        upd_kernel<<<NTOK, 128>>>(attn_out, p_cs, p_v, acol_out, xout);
        sgemm_t<64><<<dim3(2, NTOK/64), 128>>>(NTOK, 256, 128, 1, 4, xout, mlp_w1, p_h, 0, mlp_b1, 1);
        sgemm_t<64><<<gsm, 128>>>(NTOK, 128, 256, 1, 5, p_h, mlp_w2, p_h2, 0, mlp_b2, 0);
        ln_kernel<<<NTOK/8, 256>>>(p_h2, xout, ln_out_g, ln_out_b, NTOK, 1);
    }
}

// round 5
// speedup vs baseline: 2.1632x; 1.8310x over previous
#include <cuda_runtime.h>
#include <cuda_bf16.h>
#include <math.h>
#include <stdint.h>

#define HOx 64
#define WOx 64
#define DIMX 128
#define BATCH 4
#define NP (HOx*WOx)            /* 4096  */
#define NTOK (BATCH*NP)         /* 16384 */
#define NTOKIN (BATCH*128*128)  /* 65536 */

// ---------------- scratch (static device globals; no runtime alloc) ----------------
__device__ float g_xn[(size_t)NTOKIN*DIMX];
__device__ float g_k [(size_t)NTOKIN*DIMX];
__device__ float g_v [(size_t)NTOKIN*DIMX];
__device__ float g_q  [(size_t)NTOK*DIMX];
__device__ float g_qln[(size_t)NTOK*DIMX];
__device__ float g_seed[(size_t)NTOK*DIMX];
__device__ float g_h [(size_t)NTOK*2*DIMX];
__device__ float g_h2[(size_t)NTOK*DIMX];
__device__ float g_cs[NTOK];
__device__ float g_wc[9*DIMX*DIMX];
__device__ int   g_rows[9*NTOK];
// 16 weight images, each: 16384 bf16 hi + 16384 bf16 lo, row-major [n][k]
__device__ __nv_bfloat16 g_wimg[16*32768];

// ---------------- PTX helpers ----------------
__device__ __forceinline__ uint32_t smem_u32(const void* p) {
    uint32_t a;
    asm("{ .reg .u64 t; cvta.to.shared.u64 t, %1; cvt.u32.u64 %0, t; }" : "=r"(a) : "l"(p));
    return a;
}
__device__ __forceinline__ void ldsm4(uint32_t addr, uint32_t& r0, uint32_t& r1, uint32_t& r2, uint32_t& r3)
{
    asm volatile("ldmatrix.sync.aligned.m8n8.x4.shared.b16 {%0,%1,%2,%3}, [%4];"
                 : "=r"(r0), "=r"(r1), "=r"(r2), "=r"(r3) : "r"(addr));
}
__device__ __forceinline__ void mma16816(float* c, uint32_t a0, uint32_t a1, uint32_t a2, uint32_t a3,
                                         uint32_t b0, uint32_t b1)
{
    asm volatile("mma.sync.aligned.m16n8k16.row.col.f32.bf16.bf16.f32 "
                 "{%0,%1,%2,%3}, {%4,%5,%6,%7}, {%8,%9}, {%0,%1,%2,%3};"
                 : "+f"(c[0]), "+f"(c[1]), "+f"(c[2]), "+f"(c[3])
                 : "r"(a0), "r"(a1), "r"(a2), "r"(a3), "r"(b0), "r"(b1));
}

// ---------------- prep: conv weight transpose + conv row-gather table ----------------
__global__ void prep_conv(const float* __restrict__ conv_w)
{
    int i = blockIdx.x * blockDim.x + threadIdx.x;
    if (i < 9*DIMX*DIMX) {
        int kk = i / (DIMX*DIMX);
        int r  = i % (DIMX*DIMX);
        int c  = r / DIMX, dout = r % DIMX;
        int ky = kk / 3, kx = kk % 3;
        g_wc[i] = conv_w[((dout*DIMX + c)*3 + ky)*3 + kx];
    }
    if (i < 9*NTOK) {
        int kk = i / NTOK;
        int m  = i % NTOK;
        int b  = m >> 12, p = m & 4095;
        int ho = p >> 6, wo = p & 63;
        int ky = kk / 3, kx = kk % 3;
        int y = 2*ho - 1 + ky;
        int x = 2*wo - 1 + kx;
        g_rows[i] = (y >= 0 && y < 128 && x >= 0 && x < 128) ? (b*16384 + y*128 + x) : -1;
    }
}

// ---------------- prep: 16 pre-split B images, row-major [n][k] (W transposed) ----------------
__global__ void prep_img(const float* __restrict__ k_w, const float* __restrict__ v_w,
                         const float* __restrict__ q_w, const float* __restrict__ mlp_w1,
                         const float* __restrict__ mlp_w2)
{
    int e   = blockIdx.x * blockDim.x + threadIdx.x; // 0..16383
    int img = blockIdx.y;                            // 0..15
    int k = e >> 7, n = e & 127;

    const float* src; int ldn, k0, n0;
    if      (img == 0) { src = k_w;    ldn = 128; k0 = 0;   n0 = 0;   }
    else if (img == 1) { src = v_w;    ldn = 128; k0 = 0;   n0 = 0;   }
    else if (img == 2) { src = q_w;    ldn = 128; k0 = 0;   n0 = 0;   }
    else if (img == 3) { src = mlp_w1; ldn = 256; k0 = 0;   n0 = 0;   }
    else if (img == 4) { src = mlp_w1; ldn = 256; k0 = 0;   n0 = 128; }
    else if (img == 5) { src = mlp_w2; ldn = 128; k0 = 0;   n0 = 0;   }
    else if (img == 6) { src = mlp_w2; ldn = 128; k0 = 128; n0 = 0;   }
    else               { src = g_wc + (img - 7)*DIMX*DIMX; ldn = 128; k0 = 0; n0 = 0; }

    float w = src[(size_t)(k0 + k) * ldn + n0 + n];
    __nv_bfloat16 hi = __float2bfloat16(w);
    __nv_bfloat16 lo = __float2bfloat16(w - __bfloat162float(hi));
    __nv_bfloat16* dst = g_wimg + (size_t)img * 32768;
    dst[n*128 + k]         = hi;
    dst[16384 + n*128 + k] = lo;
}

// ---------------- LayerNorm over DIM=128 (one warp per row) ----------------
__global__ void ln_kernel(const float* __restrict__ in, float* __restrict__ out,
                          const float* __restrict__ gamma, const float* __restrict__ beta,
                          int nrows, int add_residual)
{
    int row  = (blockIdx.x * blockDim.x + threadIdx.x) >> 5;
    int lane = threadIdx.x & 31;
    if (row >= nrows) return;
    const float4* ip = (const float4*)(in + (size_t)row * DIMX);
    float4 v = ip[lane];
    float s  = v.x + v.y + v.z + v.w;
    float sq = v.x*v.x + v.y*v.y + v.z*v.z + v.w*v.w;
    #pragma unroll
    for (int o = 16; o > 0; o >>= 1) {
        s  += __shfl_xor_sync(0xffffffffu, s,  o);
        sq += __shfl_xor_sync(0xffffffffu, sq, o);
    }
    float mu  = s * (1.0f/DIMX);
    float var = sq * (1.0f/DIMX) - mu*mu;
    float rs  = rsqrtf(var + 1e-5f);
    float4 g4 = ((const float4*)gamma)[lane];
    float4 b4 = ((const float4*)beta)[lane];
    float4 o4;
    o4.x = (v.x - mu)*rs*g4.x + b4.x;
    o4.y = (v.y - mu)*rs*g4.y + b4.y;
    o4.z = (v.z - mu)*rs*g4.z + b4.z;
    o4.w = (v.w - mu)*rs*g4.w + b4.w;
    float4* op = (float4*)(out + (size_t)row * DIMX);
    if (add_residual) {
        float4 e = op[lane];
        o4.x += e.x; o4.y += e.y; o4.z += e.z; o4.w += e.w;
    }
    op[lane] = o4;
}

__device__ __forceinline__ float gelu_exact(float x)
{
    return 0.5f * x * (1.0f + erff(x * 0.70710678118654752f));
}

// ---------------- tensor-core GEMM via mma.sync bf16 (3-pass hi/lo split) ----------------
// C[128,128] tile per CTA.  C = sum_seg gather(A)[:,kseg] @ Bimg[seg]^T  (+bias)(+gelu)
// smem: A_hi, A_lo, B_hi, B_lo : [128][136] bf16, stride 272B (17x16B -> ldmatrix conflict-free)
#define TSTRIDE 136
#define TILE_B (128*TSTRIDE*2)     /* 34816 bytes */
#define TG_SMEM (4*TILE_B)         /* 139264 */

__global__ __launch_bounds__(256, 1)
void tgemm(int M, int lda, int nseg,
           const float* __restrict__ A,
           const int* __restrict__ rowtab,
           const __nv_bfloat16* __restrict__ Bimg,
           float* __restrict__ C, int ldc,
           const float* __restrict__ bias, int act)
{
    extern __shared__ char smem[];
    const uint32_t sb = smem_u32(smem);
    const uint32_t A_HI = sb, A_LO = sb + TILE_B, B_HI = sb + 2*TILE_B, B_LO = sb + 3*TILE_B;

    const int tid = threadIdx.x, wid = tid >> 5, lane = tid & 31;
    const int brow = blockIdx.y * 128, bcol = blockIdx.x * 128;
    const int rowbase = (wid >> 2) * 64;   // warp tile 64x32
    const int colbase = (wid & 3) * 32;

    float acc[4][4][4];
    #pragma unroll
    for (int mt = 0; mt < 4; mt++)
        #pragma unroll
        for (int nt = 0; nt < 4; nt++)
            #pragma unroll
            for (int r = 0; r < 4; r++) acc[mt][nt][r] = 0.0f;

    // per-thread ldmatrix base addresses (byte offsets within tiles)
    const uint32_t aAddr0 = (uint32_t)((rowbase + (lane & 15)) * (TSTRIDE*2) + (lane >> 4) * 16);
    const uint32_t bAddr0 = (uint32_t)((colbase + (lane & 7))  * (TSTRIDE*2) + (lane >> 3) * 16);

    for (int seg = 0; seg < nseg; seg++) {
        if (seg) __syncthreads();
        // ---- load + split A tile (128 rows x 128 k) ----
        const int kbase = rowtab ? 0 : seg * 128;
        #pragma unroll
        for (int i = 0; i < 16; i++) {
            int g   = i * 256 + tid;
            int row = g >> 5;
            int c4  = (g & 31) << 2;
            int grow = brow + row;
            int srow = rowtab ? rowtab[(size_t)seg * M + grow] : grow;
            float4 v = make_float4(0.f, 0.f, 0.f, 0.f);
            if (srow >= 0) v = *(const float4*)(A + (size_t)srow * lda + kbase + c4);
            __nv_bfloat16 h0 = __float2bfloat16(v.x), h1 = __float2bfloat16(v.y);
            __nv_bfloat16 h2 = __float2bfloat16(v.z), h3 = __float2bfloat16(v.w);
            __nv_bfloat16 l0 = __float2bfloat16(v.x - __bfloat162float(h0));
            __nv_bfloat16 l1 = __float2bfloat16(v.y - __bfloat162float(h1));
            __nv_bfloat16 l2 = __float2bfloat16(v.z - __bfloat162float(h2));
            __nv_bfloat16 l3 = __float2bfloat16(v.w - __bfloat162float(h3));
            uint32_t hp0 = (uint32_t)__bfloat16_as_ushort(h0) | ((uint32_t)__bfloat16_as_ushort(h1) << 16);
            uint32_t hp1 = (uint32_t)__bfloat16_as_ushort(h2) | ((uint32_t)__bfloat16_as_ushort(h3) << 16);
            uint32_t lp0 = (uint32_t)__bfloat16_as_ushort(l0) | ((uint32_t)__bfloat16_as_ushort(l1) << 16);
            uint32_t lp1 = (uint32_t)__bfloat16_as_ushort(l2) | ((uint32_t)__bfloat16_as_ushort(l3) << 16);
            size_t off = (size_t)row * (TSTRIDE*2) + c4 * 2;
            *(uint2*)(smem + off)          = make_uint2(hp0, hp1);
            *(uint2*)(smem + TILE_B + off) = make_uint2(lp0, lp1);
        }
        // ---- copy pre-split B image (hi 16K elems, lo 16K elems) into padded smem ----
        {
            const uint4* srcH = (const uint4*)(Bimg + ((size_t)(blockIdx.x * nseg + seg)) * 32768);
            const uint4* srcL = srcH + 2048;
            #pragma unroll
            for (int i = 0; i < 8; i++) {
                int idx = i * 256 + tid;     // uint4 index: 8 bf16 each
                int row = idx >> 4;
                int c8  = (idx & 15) << 3;
                size_t off = 2*TILE_B + (size_t)row * (TSTRIDE*2) + c8 * 2;
                *(uint4*)(smem + off)          = srcH[idx];
                *(uint4*)(smem + TILE_B + off) = srcL[idx];
            }
        }
        __syncthreads();

        // ---- 3 passes: (Ahi,Bhi), (Ahi,Blo), (Alo,Bhi) ----
        #pragma unroll
        for (int pass = 0; pass < 3; pass++) {
            const uint32_t aBase = (pass == 2 ? A_LO : A_HI) + aAddr0;
            const uint32_t bBase = (pass == 1 ? B_LO : B_HI) + bAddr0;
            #pragma unroll
            for (int kc = 0; kc < 4; kc++) {   // k32 chunks
                uint32_t bf[4][4];
                #pragma unroll
                for (int nt = 0; nt < 4; nt++)
                    ldsm4(bBase + nt*8*(TSTRIDE*2) + kc*64, bf[nt][0], bf[nt][1], bf[nt][2], bf[nt][3]);
                #pragma unroll
                for (int half = 0; half < 2; half++) {
                    uint32_t af[4][4];
                    #pragma unroll
                    for (int mt = 0; mt < 4; mt++)
                        ldsm4(aBase + mt*16*(TSTRIDE*2) + kc*64 + half*32,
                              af[mt][0], af[mt][1], af[mt][2], af[mt][3]);
                    #pragma unroll
                    for (int mt = 0; mt < 4; mt++)
                        #pragma unroll
                        for (int nt = 0; nt < 4; nt++)
                            mma16816(acc[mt][nt], af[mt][0], af[mt][1], af[mt][2], af[mt][3],
                                     bf[nt][half*2], bf[nt][half*2 + 1]);
                }
            }
        }
    }

    // ---- epilogue ----
    #pragma unroll
    for (int mt = 0; mt < 4; mt++) {
        int r0 = brow + rowbase + mt*16 + (lane >> 2);
        #pragma unroll
        for (int nt = 0; nt < 4; nt++) {
            int c = bcol + colbase + nt*8 + (lane & 3)*2;
            float v0 = acc[mt][nt][0], v1 = acc[mt][nt][1];
            float v2 = acc[mt][nt][2], v3 = acc[mt][nt][3];
            if (bias) {
                float b0 = bias[c], b1 = bias[c+1];
                v0 += b0; v1 += b1; v2 += b0; v3 += b1;
            }
            if (act) {
                v0 = gelu_exact(v0); v1 = gelu_exact(v1);
                v2 = gelu_exact(v2); v3 = gelu_exact(v3);
            }
            *(float2*)(C + (size_t)r0 * ldc + c)       = make_float2(v0, v1);
            *(float2*)(C + (size_t)(r0+8) * ldc + c)   = make_float2(v2, v3);
        }
    }
}

// ---------------- attention: dots + softmax + eps, atomic col sums ----------------
__global__ __launch_bounds__(128)
void attn_kernel(const float* __restrict__ Kv, const float* __restrict__ Qv,
                 const float* __restrict__ rpb, const float* __restrict__ tau,
                 float* __restrict__ attn_out, float* __restrict__ colsums)
{
    int bp = blockIdx.x;
    int b = bp >> 12, p = bp & 4095;
    int h = p >> 6, w = p & 63;
    int hc = min(max(h,1),62), wc = min(max(w,1),62);

    __shared__ __align__(16) float q_sh[9][128];
    int tid = threadIdx.x;
    #pragma unroll
    for (int t = 0; t < 9; t++) {
        int np = (hc + t/3 - 1)*64 + (wc + t%3 - 1);
        q_sh[t][tid] = Qv[((size_t)(b<<12) + np)*DIMX + tid];
    }
    __syncthreads();

    int g = tid >> 5, lane = tid & 31;
    int tin = (2*h + (g>>1))*128 + 2*w + (g&1);
    float4 kv = *(const float4*)(Kv + ((size_t)(b*16384 + tin))*DIMX + lane*4);

    float myd = 0.0f;
    #pragma unroll
    for (int t = 0; t < 9; t++) {
        float4 qv = *(const float4*)(&q_sh[t][lane*4]);
        float d = kv.x*qv.x + kv.y*qv.y + kv.z*qv.z + kv.w*qv.w;
        #pragma unroll
        for (int o = 16; o > 0; o >>= 1) d += __shfl_xor_sync(0xffffffffu, d, o);
        if (lane == t) myd = d;
    }

    float scale = expf(*tau);
    float z = (lane < 9) ? (myd + rpb[g*9 + lane]) * scale : -1e30f;
    float m = z;
    #pragma unroll
    for (int o = 16; o > 0; o >>= 1) m = fmaxf(m, __shfl_xor_sync(0xffffffffu, m, o));
    float e = (lane < 9) ? expf(z - m) : 0.0f;
    float s = e;
    #pragma unroll
    for (int o = 16; o > 0; o >>= 1) s += __shfl_xor_sync(0xffffffffu, s, o);

    if (lane < 9) {
        float a = e / s + 1e-6f;
        attn_out[(((size_t)(b*4 + g))*4096 + p)*9 + lane] = a;
        int np = (hc + lane/3 - 1)*64 + (wc + lane%3 - 1);
        atomicAdd(&colsums[(b<<12) + np], a);
    }
}

// ---------------- column-normalize + weighted v gather; x_out += upd ----------------
__global__ __launch_bounds__(128)
void upd_kernel(const float* __restrict__ attn_out, const float* __restrict__ colsums,
                const float* __restrict__ Vv, float* __restrict__ acol_out,
                float* __restrict__ x_out)
{
    int bp = blockIdx.x;
    int b = bp >> 12, p = bp & 4095;
    int h = p >> 6, w = p & 63;
    int hc = min(max(h,1),62), wc = min(max(w,1),62);

    __shared__ float sA[36];
    int tid = threadIdx.x;
    if (tid < 36) {
        int g = tid / 9, t = tid % 9;
        float a  = attn_out[(((size_t)(b*4 + g))*4096 + p)*9 + t];
        int np   = (hc + t/3 - 1)*64 + (wc + t%3 - 1);
        float cs = colsums[(b<<12) + np];
        float val = a / (cs + 1e-8f);
        sA[tid] = val;
        acol_out[(((size_t)(b*4 + g))*4096 + p)*9 + t] = val;
    }
    __syncthreads();

    float acc = 0.0f;
    #pragma unroll
    for (int g = 0; g < 4; g++) {
        #pragma unroll
        for (int t = 0; t < 9; t++) {
            int nh = hc + t/3 - 1, nw = wc + t%3 - 1;
            int tin = (2*nh + (g>>1))*128 + 2*nw + (g&1);
            acc += sA[g*9 + t] * Vv[((size_t)(b*16384 + tin))*DIMX + tid];
        }
    }
    x_out[((size_t)(b<<12) + p)*DIMX + tid] += acc;
}

// ---------------- launcher ----------------
extern "C" void kernel_launch(void* const* d_in, const int* in_sizes, int n_in,
                              void* d_out, int out_size)
{
    (void)in_sizes; (void)n_in; (void)out_size;
    const float* x        = (const float*)d_in[0];
    const float* conv_w   = (const float*)d_in[1];
    const float* q_w      = (const float*)d_in[2];
    const float* k_w      = (const float*)d_in[3];
    const float* v_w      = (const float*)d_in[4];
    const float* mlp_w1   = (const float*)d_in[5];
    const float* mlp_b1   = (const float*)d_in[6];
    const float* mlp_w2   = (const float*)d_in[7];
    const float* mlp_b2   = (const float*)d_in[8];
    const float* ln_in_g  = (const float*)d_in[9];
    const float* ln_in_b  = (const float*)d_in[10];
    const float* ln_out_g = (const float*)d_in[11];
    const float* ln_out_b = (const float*)d_in[12];
    const float* tau      = (const float*)d_in[13];
    const float* rpb      = (const float*)d_in[14];

    float* xout     = (float*)d_out;                       // (B, 4096, 128)
    float* attn_out = xout + (size_t)NTOK * DIMX;          // (B, 4, 64, 64, 9)
    float* acol_out = attn_out + (size_t)BATCH * 4 * NP * 9;

    float *p_xn, *p_k, *p_v, *p_q, *p_qln, *p_seed, *p_h, *p_h2, *p_cs;
    __nv_bfloat16* p_wimg;
    int* p_rows;
    cudaGetSymbolAddress((void**)&p_xn,  g_xn);
    cudaGetSymbolAddress((void**)&p_k,   g_k);
    cudaGetSymbolAddress((void**)&p_v,   g_v);
    cudaGetSymbolAddress((void**)&p_q,   g_q);
    cudaGetSymbolAddress((void**)&p_qln, g_qln);
    cudaGetSymbolAddress((void**)&p_seed,g_seed);
    cudaGetSymbolAddress((void**)&p_h,   g_h);
    cudaGetSymbolAddress((void**)&p_h2,  g_h2);
    cudaGetSymbolAddress((void**)&p_cs,  g_cs);
    cudaGetSymbolAddress((void**)&p_wimg,g_wimg);
    cudaGetSymbolAddress((void**)&p_rows,g_rows);

    static int attr_set = 0;
    if (!attr_set) {
        cudaFuncSetAttribute(tgemm, cudaFuncAttributeMaxDynamicSharedMemorySize, TG_SMEM);
        attr_set = 1;
    }

    // prep
    prep_conv<<<(9*NTOK + 255)/256, 256>>>(conv_w);
    prep_img<<<dim3(64, 16), 256>>>(k_w, v_w, q_w, mlp_w1, mlp_w2);
    // xn = LN(x, ln_in)
    ln_kernel<<<NTOKIN/8, 256>>>(x, p_xn, ln_in_g, ln_in_b, NTOKIN, 0);
    // k = xn @ k_w ; v = x @ v_w
    tgemm<<<dim3(1, NTOKIN/128), 256, TG_SMEM>>>(NTOKIN, 128, 1, p_xn, 0, p_wimg + 0*32768, p_k, 128, 0, 0);
    tgemm<<<dim3(1, NTOKIN/128), 256, TG_SMEM>>>(NTOKIN, 128, 1, x,    0, p_wimg + 1*32768, p_v, 128, 0, 0);
    // conv: 9 row-gathered K-segments, register accumulation
    tgemm<<<dim3(1, NTOK/128), 256, TG_SMEM>>>(NTOK, 128, 9, x, p_rows, p_wimg + 7*32768, p_seed, 128, 0, 0);
    // x_out = LN(seed, ln_out)
    ln_kernel<<<NTOK/8, 256>>>(p_seed, xout, ln_out_g, ln_out_b, NTOK, 0);

    for (int it = 0; it < 3; it++) {
        ln_kernel<<<NTOK/8, 256>>>(xout, p_qln, ln_out_g, ln_out_b, NTOK, 0);
        tgemm<<<dim3(1, NTOK/128), 256, TG_SMEM>>>(NTOK, 128, 1, p_qln, 0, p_wimg + 2*32768, p_q, 128, 0, 0);
        cudaMemsetAsync(p_cs, 0, NTOK * sizeof(float));
        attn_kernel<<<NTOK, 128>>>(p_k, p_q, rpb, tau, attn_out, p_cs);
        upd_kernel<<<NTOK, 128>>>(attn_out, p_cs, p_v, acol_out, xout);
        tgemm<<<dim3(2, NTOK/128), 256, TG_SMEM>>>(NTOK, 128, 1, xout, 0, p_wimg + 3*32768, p_h, 256, mlp_b1, 1);
        tgemm<<<dim3(1, NTOK/128), 256, TG_SMEM>>>(NTOK, 256, 2, p_h, 0, p_wimg + 5*32768, p_h2, 128, mlp_b2, 0);
        ln_kernel<<<NTOK/8, 256>>>(p_h2, xout, ln_out_g, ln_out_b, NTOK, 1);
    }
}

// round 6
// speedup vs baseline: 2.1905x; 1.0126x over previous
#include <cuda_runtime.h>
#include <cuda_bf16.h>
#include <math.h>
#include <stdint.h>

#define HOx 64
#define WOx 64
#define DIMX 128
#define BATCH 4
#define NP (HOx*WOx)            /* 4096  */
#define NTOK (BATCH*NP)         /* 16384 */
#define NTOKIN (BATCH*128*128)  /* 65536 */

// ---------------- scratch (static device globals; no runtime alloc) ----------------
__device__ float g_k [(size_t)NTOKIN*DIMX];
__device__ float g_v [(size_t)NTOKIN*DIMX];
__device__ float g_q  [(size_t)NTOK*DIMX];
__device__ float g_seed[(size_t)NTOK*DIMX];
__device__ float g_h [(size_t)NTOK*2*DIMX];
__device__ float g_h2[(size_t)NTOK*DIMX];
__device__ float g_cs[NTOK];
__device__ float g_wc[9*DIMX*DIMX];
__device__ int   g_rows[9*NTOK];
// 16 weight images, each: 16384 bf16 hi + 16384 bf16 lo, row-major [n][k]
__device__ __nv_bfloat16 g_wimg[16*32768];

// ---------------- PTX helpers ----------------
__device__ __forceinline__ uint32_t smem_u32(const void* p) {
    uint32_t a;
    asm("{ .reg .u64 t; cvta.to.shared.u64 t, %1; cvt.u32.u64 %0, t; }" : "=r"(a) : "l"(p));
    return a;
}
__device__ __forceinline__ void ldsm4(uint32_t addr, uint32_t& r0, uint32_t& r1, uint32_t& r2, uint32_t& r3)
{
    asm volatile("ldmatrix.sync.aligned.m8n8.x4.shared.b16 {%0,%1,%2,%3}, [%4];"
                 : "=r"(r0), "=r"(r1), "=r"(r2), "=r"(r3) : "r"(addr));
}
__device__ __forceinline__ void mma16816(float* c, uint32_t a0, uint32_t a1, uint32_t a2, uint32_t a3,
                                         uint32_t b0, uint32_t b1)
{
    asm volatile("mma.sync.aligned.m16n8k16.row.col.f32.bf16.bf16.f32 "
                 "{%0,%1,%2,%3}, {%4,%5,%6,%7}, {%8,%9}, {%0,%1,%2,%3};"
                 : "+f"(c[0]), "+f"(c[1]), "+f"(c[2]), "+f"(c[3])
                 : "r"(a0), "r"(a1), "r"(a2), "r"(a3), "r"(b0), "r"(b1));
}
__device__ __forceinline__ void cp16(uint32_t dst, const void* src)
{
    asm volatile("cp.async.ca.shared.global [%0], [%1], 16;" :: "r"(dst), "l"(src));
}
#define CP_COMMIT() asm volatile("cp.async.commit_group;" ::: "memory")
#define CP_WAIT0()  asm volatile("cp.async.wait_group 0;" ::: "memory")

// ---------------- prep: conv weight transpose + conv row-gather table ----------------
__global__ void prep_conv(const float* __restrict__ conv_w)
{
    int i = blockIdx.x * blockDim.x + threadIdx.x;
    if (i < 9*DIMX*DIMX) {
        int kk = i / (DIMX*DIMX);
        int r  = i % (DIMX*DIMX);
        int c  = r / DIMX, dout = r % DIMX;
        int ky = kk / 3, kx = kk % 3;
        g_wc[i] = conv_w[((dout*DIMX + c)*3 + ky)*3 + kx];
    }
    if (i < 9*NTOK) {
        int kk = i / NTOK;
        int m  = i % NTOK;
        int b  = m >> 12, p = m & 4095;
        int ho = p >> 6, wo = p & 63;
        int ky = kk / 3, kx = kk % 3;
        int y = 2*ho - 1 + ky;
        int x = 2*wo - 1 + kx;
        g_rows[i] = (y >= 0 && y < 128 && x >= 0 && x < 128) ? (b*16384 + y*128 + x) : -1;
    }
}

// ---------------- prep: 16 pre-split B images, row-major [n][k] (W transposed) ----------------
__global__ void prep_img(const float* __restrict__ k_w, const float* __restrict__ v_w,
                         const float* __restrict__ q_w, const float* __restrict__ mlp_w1,
                         const float* __restrict__ mlp_w2)
{
    int e   = blockIdx.x * blockDim.x + threadIdx.x; // 0..16383
    int img = blockIdx.y;                            // 0..15
    int k = e >> 7, n = e & 127;

    const float* src; int ldn, k0, n0;
    if      (img == 0) { src = k_w;    ldn = 128; k0 = 0;   n0 = 0;   }
    else if (img == 1) { src = v_w;    ldn = 128; k0 = 0;   n0 = 0;   }
    else if (img == 2) { src = q_w;    ldn = 128; k0 = 0;   n0 = 0;   }
    else if (img == 3) { src = mlp_w1; ldn = 256; k0 = 0;   n0 = 0;   }
    else if (img == 4) { src = mlp_w1; ldn = 256; k0 = 0;   n0 = 128; }
    else if (img == 5) { src = mlp_w2; ldn = 128; k0 = 0;   n0 = 0;   }
    else if (img == 6) { src = mlp_w2; ldn = 128; k0 = 128; n0 = 0;   }
    else               { src = g_wc + (img - 7)*DIMX*DIMX; ldn = 128; k0 = 0; n0 = 0; }

    float w = src[(size_t)(k0 + k) * ldn + n0 + n];
    __nv_bfloat16 hi = __float2bfloat16(w);
    __nv_bfloat16 lo = __float2bfloat16(w - __bfloat162float(hi));
    __nv_bfloat16* dst = g_wimg + (size_t)img * 32768;
    dst[n*128 + k]         = hi;
    dst[16384 + n*128 + k] = lo;
}

// ---------------- LayerNorm over DIM=128 (one warp per row) ----------------
__global__ void ln_kernel(const float* __restrict__ in, float* __restrict__ out,
                          const float* __restrict__ gamma, const float* __restrict__ beta,
                          int nrows, int add_residual)
{
    int row  = (blockIdx.x * blockDim.x + threadIdx.x) >> 5;
    int lane = threadIdx.x & 31;
    if (row >= nrows) return;
    const float4* ip = (const float4*)(in + (size_t)row * DIMX);
    float4 v = ip[lane];
    float s  = v.x + v.y + v.z + v.w;
    float sq = v.x*v.x + v.y*v.y + v.z*v.z + v.w*v.w;
    #pragma unroll
    for (int o = 16; o > 0; o >>= 1) {
        s  += __shfl_xor_sync(0xffffffffu, s,  o);
        sq += __shfl_xor_sync(0xffffffffu, sq, o);
    }
    float mu  = s * (1.0f/DIMX);
    float var = sq * (1.0f/DIMX) - mu*mu;
    float rs  = rsqrtf(var + 1e-5f);
    float4 g4 = ((const float4*)gamma)[lane];
    float4 b4 = ((const float4*)beta)[lane];
    float4 o4;
    o4.x = (v.x - mu)*rs*g4.x + b4.x;
    o4.y = (v.y - mu)*rs*g4.y + b4.y;
    o4.z = (v.z - mu)*rs*g4.z + b4.z;
    o4.w = (v.w - mu)*rs*g4.w + b4.w;
    float4* op = (float4*)(out + (size_t)row * DIMX);
    if (add_residual) {
        float4 e = op[lane];
        o4.x += e.x; o4.y += e.y; o4.z += e.z; o4.w += e.w;
    }
    op[lane] = o4;
}

__device__ __forceinline__ float gelu_exact(float x)
{
    return 0.5f * x * (1.0f + erff(x * 0.70710678118654752f));
}

// ---------------- tensor-core GEMM via mma.sync bf16 (3-pass hi/lo split) ----------------
// 512 threads, 16 warps, warp tile 32x32. Optional fused LayerNorm on A rows.
#define TSTRIDE 136
#define TILE_B (128*TSTRIDE*2)     /* 34816 bytes */
#define TG_SMEM (4*TILE_B)         /* 139264 */

__global__ __launch_bounds__(512, 1)
void tgemm(int M, int lda, int nseg,
           const float* __restrict__ A,
           const int* __restrict__ rowtab,
           const __nv_bfloat16* __restrict__ Bimg,
           float* __restrict__ C, int ldc,
           const float* __restrict__ bias, int act,
           const float* __restrict__ lng, const float* __restrict__ lnb)
{
    extern __shared__ char smem[];
    const uint32_t sb = smem_u32(smem);
    const uint32_t A_HI = sb, A_LO = sb + TILE_B, B_HI = sb + 2*TILE_B, B_LO = sb + 3*TILE_B;

    const int tid = threadIdx.x, wid = tid >> 5, lane = tid & 31;
    const int brow = blockIdx.y * 128, bcol = blockIdx.x * 128;
    const int rowbase = (wid & 3) * 32;    // warp tile 32 rows
    const int colbase = (wid >> 2) * 32;   //           x 32 cols

    float acc[2][4][4];
    #pragma unroll
    for (int mt = 0; mt < 2; mt++)
        #pragma unroll
        for (int nt = 0; nt < 4; nt++)
            #pragma unroll
            for (int r = 0; r < 4; r++) acc[mt][nt][r] = 0.0f;

    const uint32_t aAddr0 = (uint32_t)((rowbase + (lane & 15)) * (TSTRIDE*2) + (lane >> 4) * 16);
    const uint32_t bAddr0 = (uint32_t)((colbase + (lane & 7))  * (TSTRIDE*2) + (lane >> 3) * 16);

    for (int seg = 0; seg < nseg; seg++) {
        if (seg) __syncthreads();

        // ---- B image via cp.async (hi then lo), padded stride ----
        {
            const uint4* srcH = (const uint4*)(Bimg + ((size_t)(blockIdx.x * nseg + seg)) * 32768);
            #pragma unroll
            for (int i = 0; i < 4; i++) {
                int idx = i * 512 + tid;      // 0..2047 uint4 (8 bf16 each)
                int row = idx >> 4;
                int c8  = (idx & 15) << 3;
                uint32_t off = (uint32_t)(row * (TSTRIDE*2) + c8 * 2);
                cp16(B_HI + off, srcH + idx);
                cp16(B_LO + off, srcH + 2048 + idx);
            }
            CP_COMMIT();
        }

        // ---- load + split A tile (one warp per row per iteration); optional fused LN ----
        const int kbase = rowtab ? 0 : seg * 128;
        #pragma unroll
        for (int i = 0; i < 8; i++) {
            int row  = i * 16 + (wid);        // wid 0..15 -> rows i*16+wid
            int c4   = lane << 2;
            int grow = brow + row;
            int srow = rowtab ? rowtab[(size_t)seg * M + grow] : grow;
            float4 v = make_float4(0.f, 0.f, 0.f, 0.f);
            if (srow >= 0) v = *(const float4*)(A + (size_t)srow * lda + kbase + c4);
            if (lng) {
                float s  = v.x + v.y + v.z + v.w;
                float sq = v.x*v.x + v.y*v.y + v.z*v.z + v.w*v.w;
                #pragma unroll
                for (int o = 16; o > 0; o >>= 1) {
                    s  += __shfl_xor_sync(0xffffffffu, s,  o);
                    sq += __shfl_xor_sync(0xffffffffu, sq, o);
                }
                float mu  = s * (1.0f/DIMX);
                float var = sq * (1.0f/DIMX) - mu*mu;
                float rs  = rsqrtf(var + 1e-5f);
                float4 g4 = ((const float4*)lng)[lane];
                float4 b4 = ((const float4*)lnb)[lane];
                v.x = (v.x - mu)*rs*g4.x + b4.x;
                v.y = (v.y - mu)*rs*g4.y + b4.y;
                v.z = (v.z - mu)*rs*g4.z + b4.z;
                v.w = (v.w - mu)*rs*g4.w + b4.w;
            }
            __nv_bfloat16 h0 = __float2bfloat16(v.x), h1 = __float2bfloat16(v.y);
            __nv_bfloat16 h2 = __float2bfloat16(v.z), h3 = __float2bfloat16(v.w);
            __nv_bfloat16 l0 = __float2bfloat16(v.x - __bfloat162float(h0));
            __nv_bfloat16 l1 = __float2bfloat16(v.y - __bfloat162float(h1));
            __nv_bfloat16 l2 = __float2bfloat16(v.z - __bfloat162float(h2));
            __nv_bfloat16 l3 = __float2bfloat16(v.w - __bfloat162float(h3));
            uint32_t hp0 = (uint32_t)__bfloat16_as_ushort(h0) | ((uint32_t)__bfloat16_as_ushort(h1) << 16);
            uint32_t hp1 = (uint32_t)__bfloat16_as_ushort(h2) | ((uint32_t)__bfloat16_as_ushort(h3) << 16);
            uint32_t lp0 = (uint32_t)__bfloat16_as_ushort(l0) | ((uint32_t)__bfloat16_as_ushort(l1) << 16);
            uint32_t lp1 = (uint32_t)__bfloat16_as_ushort(l2) | ((uint32_t)__bfloat16_as_ushort(l3) << 16);
            size_t off = (size_t)row * (TSTRIDE*2) + c4 * 2;
            *(uint2*)(smem + off)          = make_uint2(hp0, hp1);
            *(uint2*)(smem + TILE_B + off) = make_uint2(lp0, lp1);
        }
        CP_WAIT0();
        __syncthreads();

        // ---- 3 passes: (Ahi,Bhi), (Ahi,Blo), (Alo,Bhi) ----
        #pragma unroll
        for (int pass = 0; pass < 3; pass++) {
            const uint32_t aBase = (pass == 2 ? A_LO : A_HI) + aAddr0;
            const uint32_t bBase = (pass == 1 ? B_LO : B_HI) + bAddr0;
            #pragma unroll
            for (int kc = 0; kc < 4; kc++) {   // k32 chunks
                uint32_t bf[4][4];
                #pragma unroll
                for (int nt = 0; nt < 4; nt++)
                    ldsm4(bBase + nt*8*(TSTRIDE*2) + kc*64, bf[nt][0], bf[nt][1], bf[nt][2], bf[nt][3]);
                #pragma unroll
                for (int half = 0; half < 2; half++) {
                    uint32_t af[2][4];
                    #pragma unroll
                    for (int mt = 0; mt < 2; mt++)
                        ldsm4(aBase + mt*16*(TSTRIDE*2) + kc*64 + half*32,
                              af[mt][0], af[mt][1], af[mt][2], af[mt][3]);
                    #pragma unroll
                    for (int mt = 0; mt < 2; mt++)
                        #pragma unroll
                        for (int nt = 0; nt < 4; nt++)
                            mma16816(acc[mt][nt], af[mt][0], af[mt][1], af[mt][2], af[mt][3],
                                     bf[nt][half*2], bf[nt][half*2 + 1]);
                }
            }
        }
    }

    // ---- epilogue ----
    #pragma unroll
    for (int mt = 0; mt < 2; mt++) {
        int r0 = brow + rowbase + mt*16 + (lane >> 2);
        #pragma unroll
        for (int nt = 0; nt < 4; nt++) {
            int c = bcol + colbase + nt*8 + (lane & 3)*2;
            float v0 = acc[mt][nt][0], v1 = acc[mt][nt][1];
            float v2 = acc[mt][nt][2], v3 = acc[mt][nt][3];
            if (bias) {
                float b0 = bias[c], b1 = bias[c+1];
                v0 += b0; v1 += b1; v2 += b0; v3 += b1;
            }
            if (act) {
                v0 = gelu_exact(v0); v1 = gelu_exact(v1);
                v2 = gelu_exact(v2); v3 = gelu_exact(v3);
            }
            *(float2*)(C + (size_t)r0 * ldc + c)       = make_float2(v0, v1);
            *(float2*)(C + (size_t)(r0+8) * ldc + c)   = make_float2(v2, v3);
        }
    }
}

// ---------------- attention: dots + softmax + eps, atomic col sums ----------------
__global__ __launch_bounds__(128)
void attn_kernel(const float* __restrict__ Kv, const float* __restrict__ Qv,
                 const float* __restrict__ rpb, const float* __restrict__ tau,
                 float* __restrict__ attn_out, float* __restrict__ colsums)
{
    int bp = blockIdx.x;
    int b = bp >> 12, p = bp & 4095;
    int h = p >> 6, w = p & 63;
    int hc = min(max(h,1),62), wc = min(max(w,1),62);

    __shared__ __align__(16) float q_sh[9][128];
    int tid = threadIdx.x;
    #pragma unroll
    for (int t = 0; t < 9; t++) {
        int np = (hc + t/3 - 1)*64 + (wc + t%3 - 1);
        q_sh[t][tid] = Qv[((size_t)(b<<12) + np)*DIMX + tid];
    }
    __syncthreads();

    int g = tid >> 5, lane = tid & 31;
    int tin = (2*h + (g>>1))*128 + 2*w + (g&1);
    float4 kv = *(const float4*)(Kv + ((size_t)(b*16384 + tin))*DIMX + lane*4);

    float myd = 0.0f;
    #pragma unroll
    for (int t = 0; t < 9; t++) {
        float4 qv = *(const float4*)(&q_sh[t][lane*4]);
        float d = kv.x*qv.x + kv.y*qv.y + kv.z*qv.z + kv.w*qv.w;
        #pragma unroll
        for (int o = 16; o > 0; o >>= 1) d += __shfl_xor_sync(0xffffffffu, d, o);
        if (lane == t) myd = d;
    }

    float scale = expf(*tau);
    float z = (lane < 9) ? (myd + rpb[g*9 + lane]) * scale : -1e30f;
    float m = z;
    #pragma unroll
    for (int o = 16; o > 0; o >>= 1) m = fmaxf(m, __shfl_xor_sync(0xffffffffu, m, o));
    float e = (lane < 9) ? expf(z - m) : 0.0f;
    float s = e;
    #pragma unroll
    for (int o = 16; o > 0; o >>= 1) s += __shfl_xor_sync(0xffffffffu, s, o);

    if (lane < 9) {
        float a = e / s + 1e-6f;
        attn_out[(((size_t)(b*4 + g))*4096 + p)*9 + lane] = a;
        int np = (hc + lane/3 - 1)*64 + (wc + lane%3 - 1);
        atomicAdd(&colsums[(b<<12) + np], a);
    }
}

// ---------------- column-normalize + weighted v gather; x_out += upd ----------------
__global__ __launch_bounds__(128)
void upd_kernel(const float* __restrict__ attn_out, const float* __restrict__ colsums,
                const float* __restrict__ Vv, float* __restrict__ acol_out,
                float* __restrict__ x_out)
{
    int bp = blockIdx.x;
    int b = bp >> 12, p = bp & 4095;
    int h = p >> 6, w = p & 63;
    int hc = min(max(h,1),62), wc = min(max(w,1),62);

    __shared__ float sA[36];
    int tid = threadIdx.x;
    if (tid < 36) {
        int g = tid / 9, t = tid % 9;
        float a  = attn_out[(((size_t)(b*4 + g))*4096 + p)*9 + t];
        int np   = (hc + t/3 - 1)*64 + (wc + t%3 - 1);
        float cs = colsums[(b<<12) + np];
        float val = a / (cs + 1e-8f);
        sA[tid] = val;
        acol_out[(((size_t)(b*4 + g))*4096 + p)*9 + t] = val;
    }
    __syncthreads();

    float acc = 0.0f;
    #pragma unroll
    for (int g = 0; g < 4; g++) {
        #pragma unroll
        for (int t = 0; t < 9; t++) {
            int nh = hc + t/3 - 1, nw = wc + t%3 - 1;
            int tin = (2*nh + (g>>1))*128 + 2*nw + (g&1);
            acc += sA[g*9 + t] * Vv[((size_t)(b*16384 + tin))*DIMX + tid];
        }
    }
    x_out[((size_t)(b<<12) + p)*DIMX + tid] += acc;
}

// ---------------- launcher ----------------
extern "C" void kernel_launch(void* const* d_in, const int* in_sizes, int n_in,
                              void* d_out, int out_size)
{
    (void)in_sizes; (void)n_in; (void)out_size;
    const float* x        = (const float*)d_in[0];
    const float* conv_w   = (const float*)d_in[1];
    const float* q_w      = (const float*)d_in[2];
    const float* k_w      = (const float*)d_in[3];
    const float* v_w      = (const float*)d_in[4];
    const float* mlp_w1   = (const float*)d_in[5];
    const float* mlp_b1   = (const float*)d_in[6];
    const float* mlp_w2   = (const float*)d_in[7];
    const float* mlp_b2   = (const float*)d_in[8];
    const float* ln_in_g  = (const float*)d_in[9];
    const float* ln_in_b  = (const float*)d_in[10];
    const float* ln_out_g = (const float*)d_in[11];
    const float* ln_out_b = (const float*)d_in[12];
    const float* tau      = (const float*)d_in[13];
    const float* rpb      = (const float*)d_in[14];

    float* xout     = (float*)d_out;                       // (B, 4096, 128)
    float* attn_out = xout + (size_t)NTOK * DIMX;          // (B, 4, 64, 64, 9)
    float* acol_out = attn_out + (size_t)BATCH * 4 * NP * 9;

    float *p_k, *p_v, *p_q, *p_seed, *p_h, *p_h2, *p_cs;
    __nv_bfloat16* p_wimg;
    int* p_rows;
    cudaGetSymbolAddress((void**)&p_k,   g_k);
    cudaGetSymbolAddress((void**)&p_v,   g_v);
    cudaGetSymbolAddress((void**)&p_q,   g_q);
    cudaGetSymbolAddress((void**)&p_seed,g_seed);
    cudaGetSymbolAddress((void**)&p_h,   g_h);
    cudaGetSymbolAddress((void**)&p_h2,  g_h2);
    cudaGetSymbolAddress((void**)&p_cs,  g_cs);
    cudaGetSymbolAddress((void**)&p_wimg,g_wimg);
    cudaGetSymbolAddress((void**)&p_rows,g_rows);

    static int attr_set = 0;
    if (!attr_set) {
        cudaFuncSetAttribute(tgemm, cudaFuncAttributeMaxDynamicSharedMemorySize, TG_SMEM);
        attr_set = 1;
    }

    // prep
    prep_conv<<<(9*NTOK + 255)/256, 256>>>(conv_w);
    prep_img<<<dim3(64, 16), 256>>>(k_w, v_w, q_w, mlp_w1, mlp_w2);
    // k = LN_in(x) @ k_w (LN fused) ; v = x @ v_w
    tgemm<<<dim3(1, NTOKIN/128), 512, TG_SMEM>>>(NTOKIN, 128, 1, x, 0, p_wimg + 0*32768, p_k, 128, 0, 0, ln_in_g, ln_in_b);
    tgemm<<<dim3(1, NTOKIN/128), 512, TG_SMEM>>>(NTOKIN, 128, 1, x, 0, p_wimg + 1*32768, p_v, 128, 0, 0, 0, 0);
    // conv: 9 row-gathered K-segments, register accumulation
    tgemm<<<dim3(1, NTOK/128), 512, TG_SMEM>>>(NTOK, 128, 9, x, p_rows, p_wimg + 7*32768, p_seed, 128, 0, 0, 0, 0);
    // x_out = LN(seed, ln_out)
    ln_kernel<<<NTOK/8, 256>>>(p_seed, xout, ln_out_g, ln_out_b, NTOK, 0);

    for (int it = 0; it < 3; it++) {
        // q = LN_out(xout) @ q_w (LN fused)
        tgemm<<<dim3(1, NTOK/128), 512, TG_SMEM>>>(NTOK, 128, 1, xout, 0, p_wimg + 2*32768, p_q, 128, 0, 0, ln_out_g, ln_out_b);
        cudaMemsetAsync(p_cs, 0, NTOK * sizeof(float));
        attn_kernel<<<NTOK, 128>>>(p_k, p_q, rpb, tau, attn_out, p_cs);
        upd_kernel<<<NTOK, 128>>>(attn_out, p_cs, p_v, acol_out, xout);
        tgemm<<<dim3(2, NTOK/128), 512, TG_SMEM>>>(NTOK, 128, 1, xout, 0, p_wimg + 3*32768, p_h, 256, mlp_b1, 1, 0, 0);
        tgemm<<<dim3(1, NTOK/128), 512, TG_SMEM>>>(NTOK, 256, 2, p_h, 0, p_wimg + 5*32768, p_h2, 128, mlp_b2, 0, 0, 0);
        ln_kernel<<<NTOK/8, 256>>>(p_h2, xout, ln_out_g, ln_out_b, NTOK, 1);
    }
}

// round 7
// speedup vs baseline: 2.2540x; 1.0290x over previous
#include <cuda_runtime.h>
#include <cuda_bf16.h>
#include <math.h>
#include <stdint.h>

#define HOx 64
#define WOx 64
#define DIMX 128
#define BATCH 4
#define NP (HOx*WOx)            /* 4096  */
#define NTOK (BATCH*NP)         /* 16384 */
#define NTOKIN (BATCH*128*128)  /* 65536 */

// ---------------- scratch (static device globals; no runtime alloc) ----------------
__device__ float g_k [(size_t)NTOKIN*DIMX];
__device__ float g_v [(size_t)NTOKIN*DIMX];
__device__ float g_q  [(size_t)NTOK*DIMX];
__device__ float g_seed[(size_t)NTOK*DIMX];
__device__ float g_h [(size_t)NTOK*2*DIMX];
__device__ float g_h2[(size_t)NTOK*DIMX];
__device__ float g_cs[NTOK];
__device__ float g_wc[9*DIMX*DIMX];
__device__ int   g_rows[9*NTOK];
// 16 weight images, each: 16384 bf16 hi + 16384 bf16 lo, row-major [n][k]
__device__ __nv_bfloat16 g_wimg[16*32768];

// ---------------- PTX helpers ----------------
__device__ __forceinline__ uint32_t smem_u32(const void* p) {
    uint32_t a;
    asm("{ .reg .u64 t; cvta.to.shared.u64 t, %1; cvt.u32.u64 %0, t; }" : "=r"(a) : "l"(p));
    return a;
}
__device__ __forceinline__ void ldsm4(uint32_t addr, uint32_t& r0, uint32_t& r1, uint32_t& r2, uint32_t& r3)
{
    asm volatile("ldmatrix.sync.aligned.m8n8.x4.shared.b16 {%0,%1,%2,%3}, [%4];"
                 : "=r"(r0), "=r"(r1), "=r"(r2), "=r"(r3) : "r"(addr));
}
__device__ __forceinline__ void mma16816(float* c, uint32_t a0, uint32_t a1, uint32_t a2, uint32_t a3,
                                         uint32_t b0, uint32_t b1)
{
    asm volatile("mma.sync.aligned.m16n8k16.row.col.f32.bf16.bf16.f32 "
                 "{%0,%1,%2,%3}, {%4,%5,%6,%7}, {%8,%9}, {%0,%1,%2,%3};"
                 : "+f"(c[0]), "+f"(c[1]), "+f"(c[2]), "+f"(c[3])
                 : "r"(a0), "r"(a1), "r"(a2), "r"(a3), "r"(b0), "r"(b1));
}
__device__ __forceinline__ void cp16(uint32_t dst, const void* src)
{
    asm volatile("cp.async.ca.shared.global [%0], [%1], 16;" :: "r"(dst), "l"(src));
}
#define CP_COMMIT() asm volatile("cp.async.commit_group;" ::: "memory")
#define CP_WAIT0()  asm volatile("cp.async.wait_group 0;" ::: "memory")

// ---------------- prep: conv weight transpose + conv row-gather table ----------------
__global__ void prep_conv(const float* __restrict__ conv_w)
{
    int i = blockIdx.x * blockDim.x + threadIdx.x;
    if (i < 9*DIMX*DIMX) {
        int kk = i / (DIMX*DIMX);
        int r  = i % (DIMX*DIMX);
        int c  = r / DIMX, dout = r % DIMX;
        int ky = kk / 3, kx = kk % 3;
        g_wc[i] = conv_w[((dout*DIMX + c)*3 + ky)*3 + kx];
    }
    if (i < 9*NTOK) {
        int kk = i / NTOK;
        int m  = i % NTOK;
        int b  = m >> 12, p = m & 4095;
        int ho = p >> 6, wo = p & 63;
        int ky = kk / 3, kx = kk % 3;
        int y = 2*ho - 1 + ky;
        int x = 2*wo - 1 + kx;
        g_rows[i] = (y >= 0 && y < 128 && x >= 0 && x < 128) ? (b*16384 + y*128 + x) : -1;
    }
}

// ---------------- prep: 16 pre-split B images, row-major [n][k] (W transposed) ----------------
__global__ void prep_img(const float* __restrict__ k_w, const float* __restrict__ v_w,
                         const float* __restrict__ q_w, const float* __restrict__ mlp_w1,
                         const float* __restrict__ mlp_w2)
{
    int e   = blockIdx.x * blockDim.x + threadIdx.x; // 0..16383
    int img = blockIdx.y;                            // 0..15
    int k = e >> 7, n = e & 127;

    const float* src; int ldn, k0, n0;
    if      (img == 0) { src = k_w;    ldn = 128; k0 = 0;   n0 = 0;   }
    else if (img == 1) { src = v_w;    ldn = 128; k0 = 0;   n0 = 0;   }
    else if (img == 2) { src = q_w;    ldn = 128; k0 = 0;   n0 = 0;   }
    else if (img == 3) { src = mlp_w1; ldn = 256; k0 = 0;   n0 = 0;   }
    else if (img == 4) { src = mlp_w1; ldn = 256; k0 = 0;   n0 = 128; }
    else if (img == 5) { src = mlp_w2; ldn = 128; k0 = 0;   n0 = 0;   }
    else if (img == 6) { src = mlp_w2; ldn = 128; k0 = 128; n0 = 0;   }
    else               { src = g_wc + (img - 7)*DIMX*DIMX; ldn = 128; k0 = 0; n0 = 0; }

    float w = src[(size_t)(k0 + k) * ldn + n0 + n];
    __nv_bfloat16 hi = __float2bfloat16(w);
    __nv_bfloat16 lo = __float2bfloat16(w - __bfloat162float(hi));
    __nv_bfloat16* dst = g_wimg + (size_t)img * 32768;
    dst[n*128 + k]         = hi;
    dst[16384 + n*128 + k] = lo;
}

// ---------------- LayerNorm over DIM=128 (one warp per row) ----------------
__global__ void ln_kernel(const float* __restrict__ in, float* __restrict__ out,
                          const float* __restrict__ gamma, const float* __restrict__ beta,
                          int nrows, int add_residual)
{
    int row  = (blockIdx.x * blockDim.x + threadIdx.x) >> 5;
    int lane = threadIdx.x & 31;
    if (row >= nrows) return;
    const float4* ip = (const float4*)(in + (size_t)row * DIMX);
    float4 v = ip[lane];
    float s  = v.x + v.y + v.z + v.w;
    float sq = v.x*v.x + v.y*v.y + v.z*v.z + v.w*v.w;
    #pragma unroll
    for (int o = 16; o > 0; o >>= 1) {
        s  += __shfl_xor_sync(0xffffffffu, s,  o);
        sq += __shfl_xor_sync(0xffffffffu, sq, o);
    }
    float mu  = s * (1.0f/DIMX);
    float var = sq * (1.0f/DIMX) - mu*mu;
    float rs  = rsqrtf(var + 1e-5f);
    float4 g4 = ((const float4*)gamma)[lane];
    float4 b4 = ((const float4*)beta)[lane];
    float4 o4;
    o4.x = (v.x - mu)*rs*g4.x + b4.x;
    o4.y = (v.y - mu)*rs*g4.y + b4.y;
    o4.z = (v.z - mu)*rs*g4.z + b4.z;
    o4.w = (v.w - mu)*rs*g4.w + b4.w;
    float4* op = (float4*)(out + (size_t)row * DIMX);
    if (add_residual) {
        float4 e = op[lane];
        o4.x += e.x; o4.y += e.y; o4.z += e.z; o4.w += e.w;
    }
    op[lane] = o4;
}

__device__ __forceinline__ float gelu_exact(float x)
{
    return 0.5f * x * (1.0f + erff(x * 0.70710678118654752f));
}

// ---------------- tensor-core GEMM via mma.sync bf16 (3-pass hi/lo split) ----------------
// 256 threads, 8 warps, CTA tile 64x128, warp tile 32x32, 2 CTAs/SM.
#define TSTRIDE 136
#define TILE_A (64*TSTRIDE*2)      /* 17408 bytes */
#define TILE_B (128*TSTRIDE*2)     /* 34816 bytes */
#define TG_SMEM (2*TILE_A + 2*TILE_B)  /* 104448 */

__global__ __launch_bounds__(256, 2)
void tgemm(int M, int lda, int nseg,
           const float* __restrict__ A,
           const int* __restrict__ rowtab,
           const __nv_bfloat16* __restrict__ Bimg,
           float* __restrict__ C, int ldc,
           const float* __restrict__ bias, int act,
           const float* __restrict__ lng, const float* __restrict__ lnb)
{
    extern __shared__ char smem[];
    const uint32_t sb = smem_u32(smem);
    const uint32_t A_HI = sb, A_LO = sb + TILE_A, B_HI = sb + 2*TILE_A, B_LO = sb + 2*TILE_A + TILE_B;

    const int tid = threadIdx.x, wid = tid >> 5, lane = tid & 31;
    const int brow = blockIdx.y * 64, bcol = blockIdx.x * 128;
    const int rowbase = (wid & 1) * 32;    // warp tile 32 rows
    const int colbase = (wid >> 1) * 32;   //           x 32 cols

    float acc[2][4][4];
    #pragma unroll
    for (int mt = 0; mt < 2; mt++)
        #pragma unroll
        for (int nt = 0; nt < 4; nt++)
            #pragma unroll
            for (int r = 0; r < 4; r++) acc[mt][nt][r] = 0.0f;

    const uint32_t aAddr0 = (uint32_t)((rowbase + (lane & 15)) * (TSTRIDE*2) + (lane >> 4) * 16);
    const uint32_t bAddr0 = (uint32_t)((colbase + (lane & 7))  * (TSTRIDE*2) + (lane >> 3) * 16);

    for (int seg = 0; seg < nseg; seg++) {
        if (seg) __syncthreads();

        // ---- B image via cp.async (hi then lo), padded stride ----
        {
            const uint4* srcH = (const uint4*)(Bimg + ((size_t)(blockIdx.x * nseg + seg)) * 32768);
            #pragma unroll
            for (int i = 0; i < 8; i++) {
                int idx = i * 256 + tid;      // 0..2047 uint4 (8 bf16 each)
                int row = idx >> 4;
                int c8  = (idx & 15) << 3;
                uint32_t off = (uint32_t)(row * (TSTRIDE*2) + c8 * 2);
                cp16(B_HI + off, srcH + idx);
                cp16(B_LO + off, srcH + 2048 + idx);
            }
            CP_COMMIT();
        }

        // ---- load + split A tile (64 rows); one warp per row per iteration; optional LN ----
        const int kbase = rowtab ? 0 : seg * 128;
        #pragma unroll
        for (int i = 0; i < 8; i++) {
            int row  = i * 8 + wid;           // wid 0..7 -> rows i*8+wid
            int c4   = lane << 2;
            int grow = brow + row;
            int srow = rowtab ? rowtab[(size_t)seg * M + grow] : grow;
            float4 v = make_float4(0.f, 0.f, 0.f, 0.f);
            if (srow >= 0) v = *(const float4*)(A + (size_t)srow * lda + kbase + c4);
            if (lng) {
                float s  = v.x + v.y + v.z + v.w;
                float sq = v.x*v.x + v.y*v.y + v.z*v.z + v.w*v.w;
                #pragma unroll
                for (int o = 16; o > 0; o >>= 1) {
                    s  += __shfl_xor_sync(0xffffffffu, s,  o);
                    sq += __shfl_xor_sync(0xffffffffu, sq, o);
                }
                float mu  = s * (1.0f/DIMX);
                float var = sq * (1.0f/DIMX) - mu*mu;
                float rs  = rsqrtf(var + 1e-5f);
                float4 g4 = ((const float4*)lng)[lane];
                float4 b4 = ((const float4*)lnb)[lane];
                v.x = (v.x - mu)*rs*g4.x + b4.x;
                v.y = (v.y - mu)*rs*g4.y + b4.y;
                v.z = (v.z - mu)*rs*g4.z + b4.z;
                v.w = (v.w - mu)*rs*g4.w + b4.w;
            }
            __nv_bfloat16 h0 = __float2bfloat16(v.x), h1 = __float2bfloat16(v.y);
            __nv_bfloat16 h2 = __float2bfloat16(v.z), h3 = __float2bfloat16(v.w);
            __nv_bfloat16 l0 = __float2bfloat16(v.x - __bfloat162float(h0));
            __nv_bfloat16 l1 = __float2bfloat16(v.y - __bfloat162float(h1));
            __nv_bfloat16 l2 = __float2bfloat16(v.z - __bfloat162float(h2));
            __nv_bfloat16 l3 = __float2bfloat16(v.w - __bfloat162float(h3));
            uint32_t hp0 = (uint32_t)__bfloat16_as_ushort(h0) | ((uint32_t)__bfloat16_as_ushort(h1) << 16);
            uint32_t hp1 = (uint32_t)__bfloat16_as_ushort(h2) | ((uint32_t)__bfloat16_as_ushort(h3) << 16);
            uint32_t lp0 = (uint32_t)__bfloat16_as_ushort(l0) | ((uint32_t)__bfloat16_as_ushort(l1) << 16);
            uint32_t lp1 = (uint32_t)__bfloat16_as_ushort(l2) | ((uint32_t)__bfloat16_as_ushort(l3) << 16);
            size_t off = (size_t)row * (TSTRIDE*2) + c4 * 2;
            *(uint2*)(smem + off)          = make_uint2(hp0, hp1);
            *(uint2*)(smem + TILE_A + off) = make_uint2(lp0, lp1);
        }
        CP_WAIT0();
        __syncthreads();

        // ---- 3 passes: (Ahi,Bhi), (Ahi,Blo), (Alo,Bhi) ----
        #pragma unroll
        for (int pass = 0; pass < 3; pass++) {
            const uint32_t aBase = (pass == 2 ? A_LO : A_HI) + aAddr0;
            const uint32_t bBase = (pass == 1 ? B_LO : B_HI) + bAddr0;
            #pragma unroll
            for (int kc = 0; kc < 4; kc++) {   // k32 chunks
                uint32_t bf[4][4];
                #pragma unroll
                for (int nt = 0; nt < 4; nt++)
                    ldsm4(bBase + nt*8*(TSTRIDE*2) + kc*64, bf[nt][0], bf[nt][1], bf[nt][2], bf[nt][3]);
                #pragma unroll
                for (int half = 0; half < 2; half++) {
                    uint32_t af[2][4];
                    #pragma unroll
                    for (int mt = 0; mt < 2; mt++)
                        ldsm4(aBase + mt*16*(TSTRIDE*2) + kc*64 + half*32,
                              af[mt][0], af[mt][1], af[mt][2], af[mt][3]);
                    #pragma unroll
                    for (int mt = 0; mt < 2; mt++)
                        #pragma unroll
                        for (int nt = 0; nt < 4; nt++)
                            mma16816(acc[mt][nt], af[mt][0], af[mt][1], af[mt][2], af[mt][3],
                                     bf[nt][half*2], bf[nt][half*2 + 1]);
                }
            }
        }
    }

    // ---- epilogue ----
    #pragma unroll
    for (int mt = 0; mt < 2; mt++) {
        int r0 = brow + rowbase + mt*16 + (lane >> 2);
        #pragma unroll
        for (int nt = 0; nt < 4; nt++) {
            int c = bcol + colbase + nt*8 + (lane & 3)*2;
            float v0 = acc[mt][nt][0], v1 = acc[mt][nt][1];
            float v2 = acc[mt][nt][2], v3 = acc[mt][nt][3];
            if (bias) {
                float b0 = bias[c], b1 = bias[c+1];
                v0 += b0; v1 += b1; v2 += b0; v3 += b1;
            }
            if (act) {
                v0 = gelu_exact(v0); v1 = gelu_exact(v1);
                v2 = gelu_exact(v2); v3 = gelu_exact(v3);
            }
            *(float2*)(C + (size_t)r0 * ldc + c)       = make_float2(v0, v1);
            *(float2*)(C + (size_t)(r0+8) * ldc + c)   = make_float2(v2, v3);
        }
    }
}

// ---------------- attention: dots + softmax + eps, atomic col sums ----------------
__global__ __launch_bounds__(128)
void attn_kernel(const float* __restrict__ Kv, const float* __restrict__ Qv,
                 const float* __restrict__ rpb, const float* __restrict__ tau,
                 float* __restrict__ attn_out, float* __restrict__ colsums)
{
    int bp = blockIdx.x;
    int b = bp >> 12, p = bp & 4095;
    int h = p >> 6, w = p & 63;
    int hc = min(max(h,1),62), wc = min(max(w,1),62);

    __shared__ __align__(16) float q_sh[9][128];
    int tid = threadIdx.x;
    #pragma unroll
    for (int t = 0; t < 9; t++) {
        int np = (hc + t/3 - 1)*64 + (wc + t%3 - 1);
        q_sh[t][tid] = Qv[((size_t)(b<<12) + np)*DIMX + tid];
    }
    __syncthreads();

    int g = tid >> 5, lane = tid & 31;
    int tin = (2*h + (g>>1))*128 + 2*w + (g&1);
    float4 kv = *(const float4*)(Kv + ((size_t)(b*16384 + tin))*DIMX + lane*4);

    float myd = 0.0f;
    #pragma unroll
    for (int t = 0; t < 9; t++) {
        float4 qv = *(const float4*)(&q_sh[t][lane*4]);
        float d = kv.x*qv.x + kv.y*qv.y + kv.z*qv.z + kv.w*qv.w;
        #pragma unroll
        for (int o = 16; o > 0; o >>= 1) d += __shfl_xor_sync(0xffffffffu, d, o);
        if (lane == t) myd = d;
    }

    float scale = expf(*tau);
    float z = (lane < 9) ? (myd + rpb[g*9 + lane]) * scale : -1e30f;
    float m = z;
    #pragma unroll
    for (int o = 16; o > 0; o >>= 1) m = fmaxf(m, __shfl_xor_sync(0xffffffffu, m, o));
    float e = (lane < 9) ? expf(z - m) : 0.0f;
    float s = e;
    #pragma unroll
    for (int o = 16; o > 0; o >>= 1) s += __shfl_xor_sync(0xffffffffu, s, o);

    if (lane < 9) {
        float a = e / s + 1e-6f;
        attn_out[(((size_t)(b*4 + g))*4096 + p)*9 + lane] = a;
        int np = (hc + lane/3 - 1)*64 + (wc + lane%3 - 1);
        atomicAdd(&colsums[(b<<12) + np], a);
    }
}

// ---------------- column-normalize + weighted v gather; x_out += upd ----------------
__global__ __launch_bounds__(128)
void upd_kernel(const float* __restrict__ attn_out, const float* __restrict__ colsums,
                const float* __restrict__ Vv, float* __restrict__ acol_out,
                float* __restrict__ x_out)
{
    int bp = blockIdx.x;
    int b = bp >> 12, p = bp & 4095;
    int h = p >> 6, w = p & 63;
    int hc = min(max(h,1),62), wc = min(max(w,1),62);

    __shared__ float sA[36];
    int tid = threadIdx.x;
    if (tid < 36) {
        int g = tid / 9, t = tid % 9;
        float a  = attn_out[(((size_t)(b*4 + g))*4096 + p)*9 + t];
        int np   = (hc + t/3 - 1)*64 + (wc + t%3 - 1);
        float cs = colsums[(b<<12) + np];
        float val = a / (cs + 1e-8f);
        sA[tid] = val;
        acol_out[(((size_t)(b*4 + g))*4096 + p)*9 + t] = val;
    }
    __syncthreads();

    float acc = 0.0f;
    #pragma unroll
    for (int g = 0; g < 4; g++) {
        #pragma unroll
        for (int t = 0; t < 9; t++) {
            int nh = hc + t/3 - 1, nw = wc + t%3 - 1;
            int tin = (2*nh + (g>>1))*128 + 2*nw + (g&1);
            acc += sA[g*9 + t] * Vv[((size_t)(b*16384 + tin))*DIMX + tid];
        }
    }
    x_out[((size_t)(b<<12) + p)*DIMX + tid] += acc;
}

// ---------------- launcher ----------------
extern "C" void kernel_launch(void* const* d_in, const int* in_sizes, int n_in,
                              void* d_out, int out_size)
{
    (void)in_sizes; (void)n_in; (void)out_size;
    const float* x        = (const float*)d_in[0];
    const float* conv_w   = (const float*)d_in[1];
    const float* q_w      = (const float*)d_in[2];
    const float* k_w      = (const float*)d_in[3];
    const float* v_w      = (const float*)d_in[4];
    const float* mlp_w1   = (const float*)d_in[5];
    const float* mlp_b1   = (const float*)d_in[6];
    const float* mlp_w2   = (const float*)d_in[7];
    const float* mlp_b2   = (const float*)d_in[8];
    const float* ln_in_g  = (const float*)d_in[9];
    const float* ln_in_b  = (const float*)d_in[10];
    const float* ln_out_g = (const float*)d_in[11];
    const float* ln_out_b = (const float*)d_in[12];
    const float* tau      = (const float*)d_in[13];
    const float* rpb      = (const float*)d_in[14];

    float* xout     = (float*)d_out;                       // (B, 4096, 128)
    float* attn_out = xout + (size_t)NTOK * DIMX;          // (B, 4, 64, 64, 9)
    float* acol_out = attn_out + (size_t)BATCH * 4 * NP * 9;

    float *p_k, *p_v, *p_q, *p_seed, *p_h, *p_h2, *p_cs;
    __nv_bfloat16* p_wimg;
    int* p_rows;
    cudaGetSymbolAddress((void**)&p_k,   g_k);
    cudaGetSymbolAddress((void**)&p_v,   g_v);
    cudaGetSymbolAddress((void**)&p_q,   g_q);
    cudaGetSymbolAddress((void**)&p_seed,g_seed);
    cudaGetSymbolAddress((void**)&p_h,   g_h);
    cudaGetSymbolAddress((void**)&p_h2,  g_h2);
    cudaGetSymbolAddress((void**)&p_cs,  g_cs);
    cudaGetSymbolAddress((void**)&p_wimg,g_wimg);
    cudaGetSymbolAddress((void**)&p_rows,g_rows);

    static int attr_set = 0;
    if (!attr_set) {
        cudaFuncSetAttribute(tgemm, cudaFuncAttributeMaxDynamicSharedMemorySize, TG_SMEM);
        attr_set = 1;
    }

    // prep
    prep_conv<<<(9*NTOK + 255)/256, 256>>>(conv_w);
    prep_img<<<dim3(64, 16), 256>>>(k_w, v_w, q_w, mlp_w1, mlp_w2);
    // k = LN_in(x) @ k_w (LN fused) ; v = x @ v_w
    tgemm<<<dim3(1, NTOKIN/64), 256, TG_SMEM>>>(NTOKIN, 128, 1, x, 0, p_wimg + 0*32768, p_k, 128, 0, 0, ln_in_g, ln_in_b);
    tgemm<<<dim3(1, NTOKIN/64), 256, TG_SMEM>>>(NTOKIN, 128, 1, x, 0, p_wimg + 1*32768, p_v, 128, 0, 0, 0, 0);
    // conv: 9 row-gathered K-segments, register accumulation
    tgemm<<<dim3(1, NTOK/64), 256, TG_SMEM>>>(NTOK, 128, 9, x, p_rows, p_wimg + 7*32768, p_seed, 128, 0, 0, 0, 0);
    // x_out = LN(seed, ln_out)
    ln_kernel<<<NTOK/8, 256>>>(p_seed, xout, ln_out_g, ln_out_b, NTOK, 0);

    for (int it = 0; it < 3; it++) {
        // q = LN_out(xout) @ q_w (LN fused)
        tgemm<<<dim3(1, NTOK/64), 256, TG_SMEM>>>(NTOK, 128, 1, xout, 0, p_wimg + 2*32768, p_q, 128, 0, 0, ln_out_g, ln_out_b);
        cudaMemsetAsync(p_cs, 0, NTOK * sizeof(float));
        attn_kernel<<<NTOK, 128>>>(p_k, p_q, rpb, tau, attn_out, p_cs);
        upd_kernel<<<NTOK, 128>>>(attn_out, p_cs, p_v, acol_out, xout);
        tgemm<<<dim3(2, NTOK/64), 256, TG_SMEM>>>(NTOK, 128, 1, xout, 0, p_wimg + 3*32768, p_h, 256, mlp_b1, 1, 0, 0);
        tgemm<<<dim3(1, NTOK/64), 256, TG_SMEM>>>(NTOK, 256, 2, p_h, 0, p_wimg + 5*32768, p_h2, 128, mlp_b2, 0, 0, 0);
        ln_kernel<<<NTOK/8, 256>>>(p_h2, xout, ln_out_g, ln_out_b, NTOK, 1);
    }
}